// round 2
// baseline (speedup 1.0000x reference)
#include <cuda_runtime.h>
#include <math.h>

// Problem constants
#define Bb   8
#define Ss   1370
#define Dd   1024
#define Hh   16
#define HDim 64
#define Mtot (Bb * Ss)          // 10960

// Head-major scratch [B,H,S,64] for Q,K,V  (static device arrays: allocation-free)
__device__ float g_Q[Bb * Hh * Ss * HDim];
__device__ float g_K[Bb * Hh * Ss * HDim];
__device__ float g_V[Bb * Hh * Ss * HDim];

// ---------------------------------------------------------------------------
// Kernel 1: y = x @ W^T + b   (A:[M,K] row-major, B:[N,K] row-major, both K-contig)
// 128x128 tile, BK=8, 256 threads, 8x8 per thread. grid.z selects Q/K/V.
// Epilogue writes head-major [B,H,S,64].
// ---------------------------------------------------------------------------
__global__ __launch_bounds__(256) void qkv_gemm(
    const float* __restrict__ X,
    const float* __restrict__ Wq, const float* __restrict__ bq,
    const float* __restrict__ Wk, const float* __restrict__ bk,
    const float* __restrict__ Wv, const float* __restrict__ bv)
{
    const int which = blockIdx.z;
    const float* __restrict__ W    = (which == 0) ? Wq : (which == 1) ? Wk : Wv;
    const float* __restrict__ bias = (which == 0) ? bq : (which == 1) ? bk : bv;
    float* __restrict__ Out        = (which == 0) ? g_Q : (which == 1) ? g_K : g_V;

    __shared__ float As[8][132];   // [k][m], padded: conflict-free stores, aligned reads
    __shared__ float Bs[8][132];   // [k][n]

    const int tid  = threadIdx.x;
    const int tx   = tid & 15;
    const int ty   = tid >> 4;
    const int row0 = blockIdx.y * 128;
    const int col0 = blockIdx.x * 128;

    const int lRow = tid >> 1;          // 0..127
    const int lCol = (tid & 1) << 2;    // 0 or 4

    const int  am     = row0 + lRow;
    const bool aValid = (am < Mtot);
    const float* Ap = X + (size_t)am * Dd + lCol;
    const float* Bp = W + (size_t)(col0 + lRow) * Dd + lCol;

    float acc[8][8];
#pragma unroll
    for (int i = 0; i < 8; i++)
#pragma unroll
        for (int j = 0; j < 8; j++) acc[i][j] = 0.f;

    for (int k0 = 0; k0 < Dd; k0 += 8) {
        float4 av = aValid ? *(const float4*)(Ap + k0) : make_float4(0.f, 0.f, 0.f, 0.f);
        float4 bw = *(const float4*)(Bp + k0);
        As[lCol + 0][lRow] = av.x;  As[lCol + 1][lRow] = av.y;
        As[lCol + 2][lRow] = av.z;  As[lCol + 3][lRow] = av.w;
        Bs[lCol + 0][lRow] = bw.x;  Bs[lCol + 1][lRow] = bw.y;
        Bs[lCol + 2][lRow] = bw.z;  Bs[lCol + 3][lRow] = bw.w;
        __syncthreads();
#pragma unroll
        for (int k = 0; k < 8; k++) {
            float a[8], bbv[8];
            *(float4*)(a)       = *(const float4*)&As[k][ty * 8];
            *(float4*)(a + 4)   = *(const float4*)&As[k][ty * 8 + 4];
            *(float4*)(bbv)     = *(const float4*)&Bs[k][tx * 8];
            *(float4*)(bbv + 4) = *(const float4*)&Bs[k][tx * 8 + 4];
#pragma unroll
            for (int i = 0; i < 8; i++)
#pragma unroll
                for (int j = 0; j < 8; j++)
                    acc[i][j] = fmaf(a[i], bbv[j], acc[i][j]);
        }
        __syncthreads();
    }

#pragma unroll
    for (int i = 0; i < 8; i++) {
        const int m = row0 + ty * 8 + i;
        if (m >= Mtot) continue;
        const int bi = m / Ss;
        const int s  = m - bi * Ss;
#pragma unroll
        for (int j = 0; j < 8; j++) {
            const int n = col0 + tx * 8 + j;
            const int h = n >> 6;
            const int d = n & 63;
            Out[(((size_t)(bi * Hh + h) * Ss + s) << 6) + d] = acc[i][j] + bias[n];
        }
    }
}

// ---------------------------------------------------------------------------
// Kernel 2: flash attention. Block = 64 Q rows of one (b,h). 256 threads as
// 16x16, 4x4 microtile per thread for both S=Q K^T and O += P V.
// smem: Qs[d][i] s64, Ks[d][j] s64 (overlaid with Ps[i][j] s68), Vs[j][d] s68.
// ---------------------------------------------------------------------------
#define QSTR 64
#define KSTR 64
#define PSTR 68
#define VSTR 68
#define ATTN_SMEM_BYTES ((64 * QSTR + 64 * PSTR + 64 * VSTR) * 4)   // 51200

__global__ __launch_bounds__(256) void attn_kernel(float* __restrict__ Out)
{
    extern __shared__ float sm[];
    float* smQ = sm;                         // 64*64
    float* smK = sm + 64 * QSTR;             // 64*64 (overlaid with P)
    float* smP = sm + 64 * QSTR;             // 64*68
    float* smV = sm + 64 * QSTR + 64 * PSTR; // 64*68

    const int tid = threadIdx.x;
    const int tx  = tid & 15;
    const int ty  = tid >> 4;
    const int tx4 = tx << 2;
    const int ty4 = ty << 2;
    const int qt  = blockIdx.x;
    const int h   = blockIdx.y;
    const int b   = blockIdx.z;

    const size_t bhbase = (size_t)(b * Hh + h) * Ss * HDim;

    // ---- load Q tile, transposed into smQ[d][i] (coalesced gmem reads) ----
    {
        const int r  = tid >> 2;           // tile row 0..63
        const int dq = (tid & 3) << 4;     // 0,16,32,48
        const int srow = qt * 64 + r;
        const float* src = g_Q + bhbase + (size_t)srow * HDim + dq;
#pragma unroll
        for (int c4 = 0; c4 < 4; c4++) {
            float4 v = (srow < Ss) ? *(const float4*)(src + c4 * 4)
                                   : make_float4(0.f, 0.f, 0.f, 0.f);
            const int d0 = dq + c4 * 4;
            smQ[(d0 + 0) * QSTR + r] = v.x;
            smQ[(d0 + 1) * QSTR + r] = v.y;
            smQ[(d0 + 2) * QSTR + r] = v.z;
            smQ[(d0 + 3) * QSTR + r] = v.w;
        }
    }

    float m_[4], l_[4], o_[4][4];
#pragma unroll
    for (int i = 0; i < 4; i++) {
        m_[i] = -1e30f; l_[i] = 0.f;
#pragma unroll
        for (int j = 0; j < 4; j++) o_[i][j] = 0.f;
    }

    const int NT = (Ss + 63) / 64;   // 22
    for (int kt = 0; kt < NT; kt++) {
        __syncthreads();   // prior PV finished reading smP/smV (and smQ ready on iter 0)

        // ---- load K (transposed) + V tiles ----
        {
            const int r  = tid >> 2;
            const int dq = (tid & 3) << 4;
            const int krow = kt * 64 + r;
            const bool kv = (krow < Ss);
            const float* ks = g_K + bhbase + (size_t)krow * HDim + dq;
            const float* vs = g_V + bhbase + (size_t)krow * HDim + dq;
#pragma unroll
            for (int c4 = 0; c4 < 4; c4++) {
                float4 kv4 = kv ? *(const float4*)(ks + c4 * 4)
                                : make_float4(0.f, 0.f, 0.f, 0.f);
                const int d0 = dq + c4 * 4;
                smK[(d0 + 0) * KSTR + r] = kv4.x;
                smK[(d0 + 1) * KSTR + r] = kv4.y;
                smK[(d0 + 2) * KSTR + r] = kv4.z;
                smK[(d0 + 3) * KSTR + r] = kv4.w;
            }
#pragma unroll
            for (int c4 = 0; c4 < 4; c4++) {
                float4 vv = kv ? *(const float4*)(vs + c4 * 4)
                               : make_float4(0.f, 0.f, 0.f, 0.f);
                *(float4*)&smV[r * VSTR + dq + c4 * 4] = vv;
            }
        }
        __syncthreads();

        // ---- scores: S = Q K^T (4x4 per thread) ----
        float s4[4][4];
#pragma unroll
        for (int i = 0; i < 4; i++)
#pragma unroll
            for (int j = 0; j < 4; j++) s4[i][j] = 0.f;

#pragma unroll 8
        for (int d = 0; d < 64; d++) {
            const float4 qa = *(const float4*)&smQ[d * QSTR + ty4];
            const float4 kb = *(const float4*)&smK[d * KSTR + tx4];
            const float qv[4] = {qa.x, qa.y, qa.z, qa.w};
#pragma unroll
            for (int i = 0; i < 4; i++) {
                s4[i][0] = fmaf(qv[i], kb.x, s4[i][0]);
                s4[i][1] = fmaf(qv[i], kb.y, s4[i][1]);
                s4[i][2] = fmaf(qv[i], kb.z, s4[i][2]);
                s4[i][3] = fmaf(qv[i], kb.w, s4[i][3]);
            }
        }

        // ---- online softmax (row groups = 16 contiguous lanes) ----
        const int jb = kt * 64 + tx4;
#pragma unroll
        for (int i = 0; i < 4; i++) {
            float rm = -1e30f;
#pragma unroll
            for (int j = 0; j < 4; j++) {
                float sv = s4[i][j] * 0.125f;                // 1/sqrt(64)
                if (jb + j >= Ss) sv = -1e30f;
                s4[i][j] = sv;
                rm = fmaxf(rm, sv);
            }
#pragma unroll
            for (int off = 8; off; off >>= 1)
                rm = fmaxf(rm, __shfl_xor_sync(0xffffffffu, rm, off));
            const float mnew  = fmaxf(m_[i], rm);
            const float alpha = __expf(m_[i] - mnew);
            m_[i] = mnew;
            float sum = 0.f;
#pragma unroll
            for (int j = 0; j < 4; j++) {
                const float p = __expf(s4[i][j] - mnew);
                s4[i][j] = p;                                // reuse as P
                sum += p;
            }
#pragma unroll
            for (int off = 8; off; off >>= 1)
                sum += __shfl_xor_sync(0xffffffffu, sum, off);
            l_[i] = l_[i] * alpha + sum;
#pragma unroll
            for (int j = 0; j < 4; j++) o_[i][j] *= alpha;
        }

        __syncthreads();   // everyone done reading smK before P overwrites it
#pragma unroll
        for (int i = 0; i < 4; i++)
            *(float4*)&smP[(ty4 + i) * PSTR + tx4] =
                make_float4(s4[i][0], s4[i][1], s4[i][2], s4[i][3]);
        __syncthreads();

        // ---- O += P V ----
        for (int j0 = 0; j0 < 64; j0 += 4) {
            float4 a[4];
#pragma unroll
            for (int i = 0; i < 4; i++)
                a[i] = *(const float4*)&smP[(ty4 + i) * PSTR + j0];
#pragma unroll
            for (int jc = 0; jc < 4; jc++) {
                const float4 vv = *(const float4*)&smV[(j0 + jc) * VSTR + tx4];
#pragma unroll
                for (int i = 0; i < 4; i++) {
                    const float ai = ((const float*)&a[i])[jc];
                    o_[i][0] = fmaf(ai, vv.x, o_[i][0]);
                    o_[i][1] = fmaf(ai, vv.y, o_[i][1]);
                    o_[i][2] = fmaf(ai, vv.z, o_[i][2]);
                    o_[i][3] = fmaf(ai, vv.w, o_[i][3]);
                }
            }
        }
    }

    // ---- epilogue: O /= l, write [B,S,H*hd] ----
#pragma unroll
    for (int i = 0; i < 4; i++) {
        const int s = qt * 64 + ty4 + i;
        if (s >= Ss) continue;
        const float inv = 1.f / l_[i];
        const float4 ov = make_float4(o_[i][0] * inv, o_[i][1] * inv,
                                      o_[i][2] * inv, o_[i][3] * inv);
        *(float4*)&Out[((size_t)b * Ss + s) * Dd + h * HDim + tx4] = ov;
    }
}

// ---------------------------------------------------------------------------
extern "C" void kernel_launch(void* const* d_in, const int* in_sizes, int n_in,
                              void* d_out, int out_size)
{
    const float* X  = (const float*)d_in[0];
    const float* Wq = (const float*)d_in[1];
    const float* bq = (const float*)d_in[2];
    const float* Wk = (const float*)d_in[3];
    const float* bk = (const float*)d_in[4];
    const float* Wv = (const float*)d_in[5];
    const float* bv = (const float*)d_in[6];
    float* out = (float*)d_out;

    dim3 g1(Dd / 128, (Mtot + 127) / 128, 3);   // (8, 86, 3)
    qkv_gemm<<<g1, 256>>>(X, Wq, bq, Wk, bk, Wv, bv);

    cudaFuncSetAttribute(attn_kernel, cudaFuncAttributeMaxDynamicSharedMemorySize,
                         ATTN_SMEM_BYTES);
    dim3 g2((Ss + 63) / 64, Hh, Bb);            // (22, 16, 8)
    attn_kernel<<<g2, 256, ATTN_SMEM_BYTES>>>(out);
}

// round 5
// speedup vs baseline: 1.3587x; 1.3587x over previous
#include <cuda_runtime.h>
#include <cuda_bf16.h>
#include <math.h>
#include <stdint.h>

// Problem constants
#define Bb   8
#define Ss   1370
#define Dd   1024
#define Hh   16
#define HDim 64
#define Mtot (Bb * Ss)          // 10960

// ---------------------------------------------------------------------------
// Static device scratch (allocation-free)
// ---------------------------------------------------------------------------
__device__ float g_Q[Bb * Hh * Ss * HDim];
__device__ float g_K[Bb * Hh * Ss * HDim];
__device__ float g_V[Bb * Hh * Ss * HDim];

__device__ __nv_bfloat16 g_Xhi[Mtot * Dd];
__device__ __nv_bfloat16 g_Xlo[Mtot * Dd];
__device__ __nv_bfloat16 g_Whi[3 * Dd * Dd];
__device__ __nv_bfloat16 g_Wlo[3 * Dd * Dd];

// ---------------------------------------------------------------------------
// PTX helpers — ONLY arch-generic instructions (no tcgen05: ptxas targets
// compute_103 without the 'a' feature suffix in this harness).
// ---------------------------------------------------------------------------
__device__ __forceinline__ uint32_t smem_u32(const void* p) {
    uint32_t a;
    asm("{ .reg .u64 t; cvta.to.shared.u64 t, %1; cvt.u32.u64 %0, t; }"
        : "=r"(a) : "l"(p));
    return a;
}
__device__ __forceinline__ void cp16(uint32_t d, const void* s, uint32_t sz) {
    asm volatile("cp.async.cg.shared.global [%0], [%1], 16, %2;"
                 :: "r"(d), "l"(s), "r"(sz) : "memory");
}
__device__ __forceinline__ void cp_commit() {
    asm volatile("cp.async.commit_group;" ::: "memory");
}
__device__ __forceinline__ void cp_wait1() {
    asm volatile("cp.async.wait_group 1;" ::: "memory");
}
__device__ __forceinline__ void cp_wait0() {
    asm volatile("cp.async.wait_group 0;" ::: "memory");
}
__device__ __forceinline__ void ldsm_x4(uint32_t* r, uint32_t addr) {
    asm volatile("ldmatrix.sync.aligned.m8n8.x4.shared.b16 {%0,%1,%2,%3}, [%4];"
                 : "=r"(r[0]), "=r"(r[1]), "=r"(r[2]), "=r"(r[3]) : "r"(addr));
}
__device__ __forceinline__ void ldsm_x2(uint32_t* r, uint32_t addr) {
    asm volatile("ldmatrix.sync.aligned.m8n8.x2.shared.b16 {%0,%1}, [%2];"
                 : "=r"(r[0]), "=r"(r[1]) : "r"(addr));
}
__device__ __forceinline__ void mma_bf16(float* c, const uint32_t* a, const uint32_t* b) {
    asm volatile(
        "mma.sync.aligned.m16n8k16.row.col.f32.bf16.bf16.f32 "
        "{%0,%1,%2,%3}, {%4,%5,%6,%7}, {%8,%9}, {%0,%1,%2,%3};"
        : "+f"(c[0]), "+f"(c[1]), "+f"(c[2]), "+f"(c[3])
        : "r"(a[0]), "r"(a[1]), "r"(a[2]), "r"(a[3]), "r"(b[0]), "r"(b[1]));
}

// ---------------------------------------------------------------------------
// fp32 -> bf16 hi/lo split.  mode: 0 = X, 1..3 = Wq/Wk/Wv
// ---------------------------------------------------------------------------
__global__ void split_kernel(const float* __restrict__ src, int mode, int n4)
{
    int i = blockIdx.x * blockDim.x + threadIdx.x;
    if (i >= n4) return;
    __nv_bfloat16* hi;
    __nv_bfloat16* lo;
    if (mode == 0) { hi = g_Xhi; lo = g_Xlo; }
    else {
        size_t off = (size_t)(mode - 1) * Dd * Dd;
        hi = g_Whi + off; lo = g_Wlo + off;
    }
    float4 v = ((const float4*)src)[i];
    __nv_bfloat162 h01 = __floats2bfloat162_rn(v.x, v.y);
    __nv_bfloat162 h23 = __floats2bfloat162_rn(v.z, v.w);
    float2 f01 = __bfloat1622float2(h01);
    float2 f23 = __bfloat1622float2(h23);
    __nv_bfloat162 l01 = __floats2bfloat162_rn(v.x - f01.x, v.y - f01.y);
    __nv_bfloat162 l23 = __floats2bfloat162_rn(v.z - f23.x, v.w - f23.y);
    ((__nv_bfloat162*)hi)[2 * i]     = h01;
    ((__nv_bfloat162*)hi)[2 * i + 1] = h23;
    ((__nv_bfloat162*)lo)[2 * i]     = l01;
    ((__nv_bfloat162*)lo)[2 * i + 1] = l23;
}

// ---------------------------------------------------------------------------
// QKV GEMM via mma.sync bf16, hi/lo split (3 passes -> ~1e-6 accuracy).
// CTA tile 128x128, BK=32, 256 threads = 8 warps (2 M-groups x 4 N-groups),
// warp tile 64x32 = 4x4 m16n8 accumulators.
// smem per stage: Ahi|Alo|Bhi|Blo, each 128 rows x 32 bf16, row stride 80 B
// (conflict-free for ldmatrix: 8-row walk covers all eight 16B slots mod 128).
// ---------------------------------------------------------------------------
#define ROWB     80                       // bytes per smem tile row (32 bf16 + pad)
#define TILE_B   (128 * ROWB)             // 10240
#define STAGE_B  (4 * TILE_B)             // 40960
#define GEMM_SMEM (2 * STAGE_B)           // 81920
#define NCHUNK   (Dd / 32)                // 32

__global__ __launch_bounds__(256, 1) void qkv_gemm_mma(
    const float* __restrict__ bq, const float* __restrict__ bk,
    const float* __restrict__ bv)
{
    extern __shared__ char smc[];
    const uint32_t sb = smem_u32(smc);
    const int tid = threadIdx.x;
    const int wid = tid >> 5;
    const int lid = tid & 31;

    const int nt = blockIdx.x;          // 0..7   (N tiles of 128)
    const int mt = blockIdx.y;          // 0..85  (M tiles of 128)
    const int z  = blockIdx.z;          // Q/K/V
    const int row0 = mt * 128;
    const int col0 = nt * 128;

    const __nv_bfloat16* __restrict__ Wh = g_Whi + (size_t)z * Dd * Dd;
    const __nv_bfloat16* __restrict__ Wl = g_Wlo + (size_t)z * Dd * Dd;
    const float* __restrict__ bias = (z == 0) ? bq : (z == 1) ? bk : bv;
    float* __restrict__ Out        = (z == 0) ? g_Q : (z == 1) ? g_K : g_V;

    // ---- producer addressing (all 256 threads, 8 x 16B per chunk) ----------
    // v = tid + i*256 ; tile = v>>9 (Ahi,Alo,Bhi,Blo) ; r=(v>>2)&127 ; u=v&3
    // ---- ldmatrix addressing ----------------------------------------------
    const int wm = wid & 1;             // M group (64 rows)
    const int wn = wid >> 1;            // N group (32 cols)
    const int aRow = lid & 15;          // row within m16 pair-of-8
    const int aKof = (lid >> 4) * 8;    // +8 k for mats 2,3
    const int bRow = lid & 7;
    const int bKof = ((lid >> 3) & 1) * 8;

    float acc[4][4][4];
#pragma unroll
    for (int mi = 0; mi < 4; mi++)
#pragma unroll
        for (int ni = 0; ni < 4; ni++)
#pragma unroll
            for (int q = 0; q < 4; q++) acc[mi][ni][q] = 0.f;

    // ---------------- chunk loader (cp.async) -------------------------------
    auto load_chunk = [&](int c, int s) {
        const uint32_t stg = sb + s * STAGE_B;
        const int k0 = c * 32;
#pragma unroll
        for (int i = 0; i < 8; i++) {
            const int v    = tid + i * 256;
            const int tile = v >> 9;                 // compile-time per i
            const int r    = (v >> 2) & 127;
            const int u    = v & 3;
            const uint32_t doff = stg + tile * TILE_B + r * ROWB + u * 16;
            const __nv_bfloat16* src;
            uint32_t sz = 16;
            if (tile < 2) {
                const int m = row0 + r;
                const __nv_bfloat16* base = (tile == 0) ? g_Xhi : g_Xlo;
                src = base + (size_t)((m < Mtot) ? m : 0) * Dd + k0 + u * 8;
                if (m >= Mtot) sz = 0;               // zero-fill OOB rows
            } else {
                const __nv_bfloat16* base = (tile == 2) ? Wh : Wl;
                src = base + (size_t)(col0 + r) * Dd + k0 + u * 8;
            }
            cp16(doff, src, sz);
        }
        cp_commit();
    };

    load_chunk(0, 0);

    for (int c = 0; c < NCHUNK; c++) {
        if (c + 1 < NCHUNK) { load_chunk(c + 1, (c + 1) & 1); cp_wait1(); }
        else                { cp_wait0(); }
        __syncthreads();

        const uint32_t stg = sb + (c & 1) * STAGE_B;
        const uint32_t aHi = stg + (wm * 64 + aRow) * ROWB + aKof * 2;
        const uint32_t bHi = stg + 2 * TILE_B + (wn * 32 + bRow) * ROWB + bKof * 2;

#pragma unroll
        for (int kk = 0; kk < 32; kk += 16) {
            uint32_t Ah[4][4], Al[4][4], Bh[4][2], Bl[4][2];
#pragma unroll
            for (int mi = 0; mi < 4; mi++) {
                const uint32_t a = aHi + mi * (16 * ROWB) + kk * 2;
                ldsm_x4(Ah[mi], a);
                ldsm_x4(Al[mi], a + TILE_B);
            }
#pragma unroll
            for (int ni = 0; ni < 4; ni++) {
                const uint32_t b = bHi + ni * (8 * ROWB) + kk * 2;
                ldsm_x2(Bh[ni], b);
                ldsm_x2(Bl[ni], b + TILE_B);
            }
#pragma unroll
            for (int mi = 0; mi < 4; mi++)
#pragma unroll
                for (int ni = 0; ni < 4; ni++) {
                    mma_bf16(acc[mi][ni], Ah[mi], Bh[ni]);   // hi*hi
                    mma_bf16(acc[mi][ni], Ah[mi], Bl[ni]);   // hi*lo
                    mma_bf16(acc[mi][ni], Al[mi], Bh[ni]);   // lo*hi
                }
        }
        __syncthreads();
    }

    // ---------------- epilogue: bias + head-major scatter -------------------
    const int g = lid >> 2;
    const int t = lid & 3;
#pragma unroll
    for (int mi = 0; mi < 4; mi++) {
        const int m0 = row0 + wm * 64 + mi * 16 + g;
#pragma unroll
        for (int half = 0; half < 2; half++) {
            const int m = m0 + half * 8;
            if (m >= Mtot) continue;
            const int bix  = m / Ss;
            const int srow = m - bix * Ss;
#pragma unroll
            for (int ni = 0; ni < 4; ni++) {
                const int n = col0 + wn * 32 + ni * 8 + t * 2;
                const int h = n >> 6;
                const int d = n & 63;
                float2 o;
                o.x = acc[mi][ni][half * 2 + 0] + __ldg(bias + n);
                o.y = acc[mi][ni][half * 2 + 1] + __ldg(bias + n + 1);
                *(float2*)&Out[(((size_t)(bix * Hh + h) * Ss + srow) << 6) + d] = o;
            }
        }
    }
}

// ---------------------------------------------------------------------------
// Kernel 2: flash attention (unchanged)
// ---------------------------------------------------------------------------
#define QSTR 64
#define KSTR 64
#define PSTR 68
#define VSTR 68
#define ATTN_SMEM_BYTES ((64 * QSTR + 64 * PSTR + 64 * VSTR) * 4)   // 51200

__global__ __launch_bounds__(256) void attn_kernel(float* __restrict__ Out)
{
    extern __shared__ float sm[];
    float* smQ = sm;
    float* smK = sm + 64 * QSTR;
    float* smP = sm + 64 * QSTR;
    float* smV = sm + 64 * QSTR + 64 * PSTR;

    const int tid = threadIdx.x;
    const int tx  = tid & 15;
    const int ty  = tid >> 4;
    const int tx4 = tx << 2;
    const int ty4 = ty << 2;
    const int qt  = blockIdx.x;
    const int h   = blockIdx.y;
    const int b   = blockIdx.z;

    const size_t bhbase = (size_t)(b * Hh + h) * Ss * HDim;

    {
        const int r  = tid >> 2;
        const int dq = (tid & 3) << 4;
        const int srow = qt * 64 + r;
        const float* src = g_Q + bhbase + (size_t)srow * HDim + dq;
#pragma unroll
        for (int c4 = 0; c4 < 4; c4++) {
            float4 v = (srow < Ss) ? *(const float4*)(src + c4 * 4)
                                   : make_float4(0.f, 0.f, 0.f, 0.f);
            const int d0 = dq + c4 * 4;
            smQ[(d0 + 0) * QSTR + r] = v.x;
            smQ[(d0 + 1) * QSTR + r] = v.y;
            smQ[(d0 + 2) * QSTR + r] = v.z;
            smQ[(d0 + 3) * QSTR + r] = v.w;
        }
    }

    float m_[4], l_[4], o_[4][4];
#pragma unroll
    for (int i = 0; i < 4; i++) {
        m_[i] = -1e30f; l_[i] = 0.f;
#pragma unroll
        for (int j = 0; j < 4; j++) o_[i][j] = 0.f;
    }

    const int NT = (Ss + 63) / 64;
    for (int kt = 0; kt < NT; kt++) {
        __syncthreads();
        {
            const int r  = tid >> 2;
            const int dq = (tid & 3) << 4;
            const int krow = kt * 64 + r;
            const bool kv = (krow < Ss);
            const float* ks = g_K + bhbase + (size_t)krow * HDim + dq;
            const float* vs = g_V + bhbase + (size_t)krow * HDim + dq;
#pragma unroll
            for (int c4 = 0; c4 < 4; c4++) {
                float4 kv4 = kv ? *(const float4*)(ks + c4 * 4)
                                : make_float4(0.f, 0.f, 0.f, 0.f);
                const int d0 = dq + c4 * 4;
                smK[(d0 + 0) * KSTR + r] = kv4.x;
                smK[(d0 + 1) * KSTR + r] = kv4.y;
                smK[(d0 + 2) * KSTR + r] = kv4.z;
                smK[(d0 + 3) * KSTR + r] = kv4.w;
            }
#pragma unroll
            for (int c4 = 0; c4 < 4; c4++) {
                float4 vv = kv ? *(const float4*)(vs + c4 * 4)
                               : make_float4(0.f, 0.f, 0.f, 0.f);
                *(float4*)&smV[r * VSTR + dq + c4 * 4] = vv;
            }
        }
        __syncthreads();

        float s4[4][4];
#pragma unroll
        for (int i = 0; i < 4; i++)
#pragma unroll
            for (int j = 0; j < 4; j++) s4[i][j] = 0.f;

#pragma unroll 8
        for (int d = 0; d < 64; d++) {
            const float4 qa = *(const float4*)&smQ[d * QSTR + ty4];
            const float4 kb = *(const float4*)&smK[d * KSTR + tx4];
            const float qv[4] = {qa.x, qa.y, qa.z, qa.w};
#pragma unroll
            for (int i = 0; i < 4; i++) {
                s4[i][0] = fmaf(qv[i], kb.x, s4[i][0]);
                s4[i][1] = fmaf(qv[i], kb.y, s4[i][1]);
                s4[i][2] = fmaf(qv[i], kb.z, s4[i][2]);
                s4[i][3] = fmaf(qv[i], kb.w, s4[i][3]);
            }
        }

        const int jb = kt * 64 + tx4;
#pragma unroll
        for (int i = 0; i < 4; i++) {
            float rm = -1e30f;
#pragma unroll
            for (int j = 0; j < 4; j++) {
                float sv = s4[i][j] * 0.125f;
                if (jb + j >= Ss) sv = -1e30f;
                s4[i][j] = sv;
                rm = fmaxf(rm, sv);
            }
#pragma unroll
            for (int off = 8; off; off >>= 1)
                rm = fmaxf(rm, __shfl_xor_sync(0xffffffffu, rm, off));
            const float mnew  = fmaxf(m_[i], rm);
            const float alpha = __expf(m_[i] - mnew);
            m_[i] = mnew;
            float sum = 0.f;
#pragma unroll
            for (int j = 0; j < 4; j++) {
                const float p = __expf(s4[i][j] - mnew);
                s4[i][j] = p;
                sum += p;
            }
#pragma unroll
            for (int off = 8; off; off >>= 1)
                sum += __shfl_xor_sync(0xffffffffu, sum, off);
            l_[i] = l_[i] * alpha + sum;
#pragma unroll
            for (int j = 0; j < 4; j++) o_[i][j] *= alpha;
        }

        __syncthreads();
#pragma unroll
        for (int i = 0; i < 4; i++)
            *(float4*)&smP[(ty4 + i) * PSTR + tx4] =
                make_float4(s4[i][0], s4[i][1], s4[i][2], s4[i][3]);
        __syncthreads();

        for (int j0 = 0; j0 < 64; j0 += 4) {
            float4 a[4];
#pragma unroll
            for (int i = 0; i < 4; i++)
                a[i] = *(const float4*)&smP[(ty4 + i) * PSTR + j0];
#pragma unroll
            for (int jc = 0; jc < 4; jc++) {
                const float4 vv = *(const float4*)&smV[(j0 + jc) * VSTR + tx4];
#pragma unroll
                for (int i = 0; i < 4; i++) {
                    const float ai = ((const float*)&a[i])[jc];
                    o_[i][0] = fmaf(ai, vv.x, o_[i][0]);
                    o_[i][1] = fmaf(ai, vv.y, o_[i][1]);
                    o_[i][2] = fmaf(ai, vv.z, o_[i][2]);
                    o_[i][3] = fmaf(ai, vv.w, o_[i][3]);
                }
            }
        }
    }

#pragma unroll
    for (int i = 0; i < 4; i++) {
        const int s = qt * 64 + ty4 + i;
        if (s >= Ss) continue;
        const float inv = 1.f / l_[i];
        const float4 ov = make_float4(o_[i][0] * inv, o_[i][1] * inv,
                                      o_[i][2] * inv, o_[i][3] * inv);
        *(float4*)&Out[((size_t)b * Ss + s) * Dd + h * HDim + tx4] = ov;
    }
}

// ---------------------------------------------------------------------------
extern "C" void kernel_launch(void* const* d_in, const int* in_sizes, int n_in,
                              void* d_out, int out_size)
{
    const float* X  = (const float*)d_in[0];
    const float* Wq = (const float*)d_in[1];
    const float* bq = (const float*)d_in[2];
    const float* Wk = (const float*)d_in[3];
    const float* bk = (const float*)d_in[4];
    const float* Wv = (const float*)d_in[5];
    const float* bv = (const float*)d_in[6];
    float* out = (float*)d_out;

    // 1) split fp32 -> bf16 hi/lo
    const int nX4 = Mtot * Dd / 4;
    const int nW4 = Dd * Dd / 4;
    split_kernel<<<(nX4 + 255) / 256, 256>>>(X, 0, nX4);
    split_kernel<<<(nW4 + 255) / 256, 256>>>(Wq, 1, nW4);
    split_kernel<<<(nW4 + 255) / 256, 256>>>(Wk, 2, nW4);
    split_kernel<<<(nW4 + 255) / 256, 256>>>(Wv, 3, nW4);

    // 2) mma.sync QKV GEMM
    cudaFuncSetAttribute(qkv_gemm_mma, cudaFuncAttributeMaxDynamicSharedMemorySize,
                         GEMM_SMEM);
    dim3 gg(Dd / 128, (Mtot + 127) / 128, 3);   // (8, 86, 3)
    qkv_gemm_mma<<<gg, 256, GEMM_SMEM>>>(bq, bk, bv);

    // 3) attention (unchanged)
    cudaFuncSetAttribute(attn_kernel, cudaFuncAttributeMaxDynamicSharedMemorySize,
                         ATTN_SMEM_BYTES);
    dim3 g2((Ss + 63) / 64, Hh, Bb);            // (22, 16, 8)
    attn_kernel<<<g2, 256, ATTN_SMEM_BYTES>>>(out);
}

// round 6
// speedup vs baseline: 2.8167x; 2.0731x over previous
#include <cuda_runtime.h>
#include <cuda_bf16.h>
#include <math.h>
#include <stdint.h>

// Problem constants
#define Bb   8
#define Ss   1370
#define Dd   1024
#define Hh   16
#define HDim 64
#define Mtot (Bb * Ss)          // 10960

// ---------------------------------------------------------------------------
// Static device scratch (allocation-free)
// ---------------------------------------------------------------------------
__device__ __nv_bfloat16 g_Xhi[Mtot * Dd];
__device__ __nv_bfloat16 g_Xlo[Mtot * Dd];
__device__ __nv_bfloat16 g_Whi[3 * Dd * Dd];
__device__ __nv_bfloat16 g_Wlo[3 * Dd * Dd];

// Q/K/V in bf16 hi/lo, head-major [B,H,S,64]
__device__ __nv_bfloat16 g_Qh[Bb * Hh * Ss * HDim];
__device__ __nv_bfloat16 g_Ql[Bb * Hh * Ss * HDim];
__device__ __nv_bfloat16 g_Kh[Bb * Hh * Ss * HDim];
__device__ __nv_bfloat16 g_Kl[Bb * Hh * Ss * HDim];
__device__ __nv_bfloat16 g_Vh[Bb * Hh * Ss * HDim];
__device__ __nv_bfloat16 g_Vl[Bb * Hh * Ss * HDim];

// ---------------------------------------------------------------------------
// PTX helpers — arch-generic only (no tcgen05 in this harness's ptx target)
// ---------------------------------------------------------------------------
__device__ __forceinline__ uint32_t smem_u32(const void* p) {
    uint32_t a;
    asm("{ .reg .u64 t; cvta.to.shared.u64 t, %1; cvt.u32.u64 %0, t; }"
        : "=r"(a) : "l"(p));
    return a;
}
__device__ __forceinline__ void cp16(uint32_t d, const void* s, uint32_t sz) {
    asm volatile("cp.async.cg.shared.global [%0], [%1], 16, %2;"
                 :: "r"(d), "l"(s), "r"(sz) : "memory");
}
__device__ __forceinline__ void cp_commit() {
    asm volatile("cp.async.commit_group;" ::: "memory");
}
__device__ __forceinline__ void cp_wait1() {
    asm volatile("cp.async.wait_group 1;" ::: "memory");
}
__device__ __forceinline__ void cp_wait0() {
    asm volatile("cp.async.wait_group 0;" ::: "memory");
}
__device__ __forceinline__ void ldsm_x4(uint32_t* r, uint32_t addr) {
    asm volatile("ldmatrix.sync.aligned.m8n8.x4.shared.b16 {%0,%1,%2,%3}, [%4];"
                 : "=r"(r[0]), "=r"(r[1]), "=r"(r[2]), "=r"(r[3]) : "r"(addr));
}
__device__ __forceinline__ void ldsm_x4t(uint32_t* r, uint32_t addr) {
    asm volatile("ldmatrix.sync.aligned.m8n8.x4.trans.shared.b16 {%0,%1,%2,%3}, [%4];"
                 : "=r"(r[0]), "=r"(r[1]), "=r"(r[2]), "=r"(r[3]) : "r"(addr));
}
__device__ __forceinline__ void ldsm_x2(uint32_t* r, uint32_t addr) {
    asm volatile("ldmatrix.sync.aligned.m8n8.x2.shared.b16 {%0,%1}, [%2];"
                 : "=r"(r[0]), "=r"(r[1]) : "r"(addr));
}
__device__ __forceinline__ void mma_bf16(float* c, const uint32_t* a, const uint32_t* b) {
    asm volatile(
        "mma.sync.aligned.m16n8k16.row.col.f32.bf16.bf16.f32 "
        "{%0,%1,%2,%3}, {%4,%5,%6,%7}, {%8,%9}, {%0,%1,%2,%3};"
        : "+f"(c[0]), "+f"(c[1]), "+f"(c[2]), "+f"(c[3])
        : "r"(a[0]), "r"(a[1]), "r"(a[2]), "r"(a[3]), "r"(b[0]), "r"(b[1]));
}
__device__ __forceinline__ uint32_t pack_bf16x2(float x, float y) {
    __nv_bfloat162 h = __floats2bfloat162_rn(x, y);
    return *reinterpret_cast<uint32_t*>(&h);
}

// ---------------------------------------------------------------------------
// fp32 -> bf16 hi/lo split.  mode: 0 = X, 1..3 = Wq/Wk/Wv
// ---------------------------------------------------------------------------
__global__ void split_kernel(const float* __restrict__ src, int mode, int n4)
{
    int i = blockIdx.x * blockDim.x + threadIdx.x;
    if (i >= n4) return;
    __nv_bfloat16* hi;
    __nv_bfloat16* lo;
    if (mode == 0) { hi = g_Xhi; lo = g_Xlo; }
    else {
        size_t off = (size_t)(mode - 1) * Dd * Dd;
        hi = g_Whi + off; lo = g_Wlo + off;
    }
    float4 v = ((const float4*)src)[i];
    __nv_bfloat162 h01 = __floats2bfloat162_rn(v.x, v.y);
    __nv_bfloat162 h23 = __floats2bfloat162_rn(v.z, v.w);
    float2 f01 = __bfloat1622float2(h01);
    float2 f23 = __bfloat1622float2(h23);
    __nv_bfloat162 l01 = __floats2bfloat162_rn(v.x - f01.x, v.y - f01.y);
    __nv_bfloat162 l23 = __floats2bfloat162_rn(v.z - f23.x, v.w - f23.y);
    ((__nv_bfloat162*)hi)[2 * i]     = h01;
    ((__nv_bfloat162*)hi)[2 * i + 1] = h23;
    ((__nv_bfloat162*)lo)[2 * i]     = l01;
    ((__nv_bfloat162*)lo)[2 * i + 1] = l23;
}

// ---------------------------------------------------------------------------
// QKV GEMM via mma.sync bf16, hi/lo split (3 passes).
// CTA 128x128, BK=32, 8 warps (2Mx4N), warp 64x32.
// Epilogue: +bias, then write bf16 hi/lo head-major.
// ---------------------------------------------------------------------------
#define ROWB     80
#define TILE_B   (128 * ROWB)
#define STAGE_B  (4 * TILE_B)
#define GEMM_SMEM (2 * STAGE_B)
#define NCHUNK   (Dd / 32)

__global__ __launch_bounds__(256, 1) void qkv_gemm_mma(
    const float* __restrict__ bq, const float* __restrict__ bk,
    const float* __restrict__ bv)
{
    extern __shared__ char smc[];
    const uint32_t sb = smem_u32(smc);
    const int tid = threadIdx.x;
    const int wid = tid >> 5;
    const int lid = tid & 31;

    const int nt = blockIdx.x;
    const int mt = blockIdx.y;
    const int z  = blockIdx.z;
    const int row0 = mt * 128;
    const int col0 = nt * 128;

    const __nv_bfloat16* __restrict__ Wh = g_Whi + (size_t)z * Dd * Dd;
    const __nv_bfloat16* __restrict__ Wl = g_Wlo + (size_t)z * Dd * Dd;
    const float* __restrict__ bias = (z == 0) ? bq : (z == 1) ? bk : bv;
    __nv_bfloat16* __restrict__ OutH = (z == 0) ? g_Qh : (z == 1) ? g_Kh : g_Vh;
    __nv_bfloat16* __restrict__ OutL = (z == 0) ? g_Ql : (z == 1) ? g_Kl : g_Vl;

    const int wm = wid & 1;
    const int wn = wid >> 1;
    const int aRow = lid & 15;
    const int aKof = (lid >> 4) * 8;
    const int bRow = lid & 7;
    const int bKof = ((lid >> 3) & 1) * 8;

    float acc[4][4][4];
#pragma unroll
    for (int mi = 0; mi < 4; mi++)
#pragma unroll
        for (int ni = 0; ni < 4; ni++)
#pragma unroll
            for (int q = 0; q < 4; q++) acc[mi][ni][q] = 0.f;

    auto load_chunk = [&](int c, int s) {
        const uint32_t stg = sb + s * STAGE_B;
        const int k0 = c * 32;
#pragma unroll
        for (int i = 0; i < 8; i++) {
            const int v    = tid + i * 256;
            const int tile = v >> 9;
            const int r    = (v >> 2) & 127;
            const int u    = v & 3;
            const uint32_t doff = stg + tile * TILE_B + r * ROWB + u * 16;
            const __nv_bfloat16* src;
            uint32_t sz = 16;
            if (tile < 2) {
                const int m = row0 + r;
                const __nv_bfloat16* base = (tile == 0) ? g_Xhi : g_Xlo;
                src = base + (size_t)((m < Mtot) ? m : 0) * Dd + k0 + u * 8;
                if (m >= Mtot) sz = 0;
            } else {
                const __nv_bfloat16* base = (tile == 2) ? Wh : Wl;
                src = base + (size_t)(col0 + r) * Dd + k0 + u * 8;
            }
            cp16(doff, src, sz);
        }
        cp_commit();
    };

    load_chunk(0, 0);

    for (int c = 0; c < NCHUNK; c++) {
        if (c + 1 < NCHUNK) { load_chunk(c + 1, (c + 1) & 1); cp_wait1(); }
        else                { cp_wait0(); }
        __syncthreads();

        const uint32_t stg = sb + (c & 1) * STAGE_B;
        const uint32_t aHi = stg + (wm * 64 + aRow) * ROWB + aKof * 2;
        const uint32_t bHi = stg + 2 * TILE_B + (wn * 32 + bRow) * ROWB + bKof * 2;

#pragma unroll
        for (int kk = 0; kk < 32; kk += 16) {
            uint32_t Ah[4][4], Al[4][4], Bh[4][2], Bl[4][2];
#pragma unroll
            for (int mi = 0; mi < 4; mi++) {
                const uint32_t a = aHi + mi * (16 * ROWB) + kk * 2;
                ldsm_x4(Ah[mi], a);
                ldsm_x4(Al[mi], a + TILE_B);
            }
#pragma unroll
            for (int ni = 0; ni < 4; ni++) {
                const uint32_t b = bHi + ni * (8 * ROWB) + kk * 2;
                ldsm_x2(Bh[ni], b);
                ldsm_x2(Bl[ni], b + TILE_B);
            }
#pragma unroll
            for (int mi = 0; mi < 4; mi++)
#pragma unroll
                for (int ni = 0; ni < 4; ni++) {
                    mma_bf16(acc[mi][ni], Ah[mi], Bh[ni]);
                    mma_bf16(acc[mi][ni], Ah[mi], Bl[ni]);
                    mma_bf16(acc[mi][ni], Al[mi], Bh[ni]);
                }
        }
        __syncthreads();
    }

    // epilogue: bias, split into bf16 hi/lo, head-major scatter
    const int g = lid >> 2;
    const int t = lid & 3;
#pragma unroll
    for (int mi = 0; mi < 4; mi++) {
        const int m0 = row0 + wm * 64 + mi * 16 + g;
#pragma unroll
        for (int half = 0; half < 2; half++) {
            const int m = m0 + half * 8;
            if (m >= Mtot) continue;
            const int bix  = m / Ss;
            const int srow = m - bix * Ss;
#pragma unroll
            for (int ni = 0; ni < 4; ni++) {
                const int n = col0 + wn * 32 + ni * 8 + t * 2;
                const int h = n >> 6;
                const int d = n & 63;
                const float vx = acc[mi][ni][half * 2 + 0] + __ldg(bias + n);
                const float vy = acc[mi][ni][half * 2 + 1] + __ldg(bias + n + 1);
                __nv_bfloat162 h2 = __floats2bfloat162_rn(vx, vy);
                float2 f = __bfloat1622float2(h2);
                __nv_bfloat162 l2 = __floats2bfloat162_rn(vx - f.x, vy - f.y);
                const size_t idx = (((size_t)(bix * Hh + h) * Ss + srow) << 6) + d;
                *(uint32_t*)&OutH[idx] = *(uint32_t*)&h2;
                *(uint32_t*)&OutL[idx] = *(uint32_t*)&l2;
            }
        }
    }
}

// ---------------------------------------------------------------------------
// Flash attention via mma.sync, split precision.
// CTA = 128 Q rows of one (b,h); 8 warps x 16 rows; 128-key tiles (11).
// smem: Qh|Ql (36KB) + 2 stages x (Kh|Kl|Vh|Vl) (72KB each). Row stride 144B.
// ---------------------------------------------------------------------------
#define AKSTR   144
#define ATILE   (128 * AKSTR)            // 18432
#define ASTAGE  (4 * ATILE)              // 73728
#define AQ      (2 * ATILE)              // 36864
#define ATTN_SMEM (AQ + 2 * ASTAGE)      // 184320
#define NTIL    ((Ss + 127) / 128)       // 11

__global__ __launch_bounds__(256, 1) void attn_mma(float* __restrict__ Out)
{
    extern __shared__ char smc[];
    const uint32_t sb = smem_u32(smc);
    const int tid = threadIdx.x;
    const int wid = tid >> 5;
    const int lid = tid & 31;
    const int qt  = blockIdx.x;
    const int h   = blockIdx.y;
    const int b   = blockIdx.z;

    const size_t bh = (size_t)(b * Hh + h) * Ss * HDim;

    // ---- async loaders ------------------------------------------------------
    auto load_q = [&]() {
#pragma unroll
        for (int i = 0; i < 8; i++) {
            const int u    = tid + i * 256;
            const int tile = u >> 10;           // 0 = hi, 1 = lo
            const int r    = (u >> 3) & 127;
            const int uc   = u & 7;
            const int row  = qt * 128 + r;
            const bool v   = (row < Ss);
            const __nv_bfloat16* g =
                (tile ? g_Ql : g_Qh) + bh + (size_t)(v ? row : 0) * HDim + uc * 8;
            cp16(sb + tile * ATILE + r * AKSTR + uc * 16, g, v ? 16u : 0u);
        }
    };
    auto load_kv = [&](int kt, int s) {
        const uint32_t base = sb + AQ + s * ASTAGE;
#pragma unroll
        for (int i = 0; i < 16; i++) {
            const int u    = tid + i * 256;
            const int tile = u >> 10;           // Kh,Kl,Vh,Vl
            const int r    = (u >> 3) & 127;
            const int uc   = u & 7;
            const int key  = kt * 128 + r;
            const bool v   = (key < Ss);
            const __nv_bfloat16* g =
                (tile == 0 ? g_Kh : tile == 1 ? g_Kl : tile == 2 ? g_Vh : g_Vl)
                + bh + (size_t)(v ? key : 0) * HDim + uc * 8;
            cp16(base + tile * ATILE + r * AKSTR + uc * 16, g, v ? 16u : 0u);
        }
    };

    load_q();
    load_kv(0, 0);
    cp_commit();

    // ---- per-lane fragment offsets -----------------------------------------
    const int t = lid & 3;
    const int g = lid >> 2;
    // K-type (B non-trans): row bit = lane bit4, col bit = lane bit3
    const int kRow  = (lid & 7) + ((lid >> 4) & 1) * 8;
    const int kColB = ((lid >> 3) & 1) * 16;
    // V-type (B trans) and Q (A): row bit = bit3, col bit = bit4
    const int vRow  = (lid & 7) + ((lid >> 3) & 1) * 8;
    const int vColB = ((lid >> 4) & 1) * 16;

    float m0_ = -1e30f, m1_ = -1e30f, l0_ = 0.f, l1_ = 0.f;
    float O[8][4];
#pragma unroll
    for (int ni = 0; ni < 8; ni++)
#pragma unroll
        for (int q = 0; q < 4; q++) O[ni][q] = 0.f;

    uint32_t Qh[4][4], Ql[4][4];

    for (int kt = 0; kt < NTIL; kt++) {
        if (kt + 1 < NTIL) { load_kv(kt + 1, (kt + 1) & 1); cp_commit(); cp_wait1(); }
        else               { cp_wait0(); }
        __syncthreads();

        if (kt == 0) {
            const uint32_t qb = sb + (wid * 16 + vRow) * AKSTR + vColB;
#pragma unroll
            for (int ks = 0; ks < 4; ks++) {
                ldsm_x4(Qh[ks], qb + ks * 32);
                ldsm_x4(Ql[ks], qb + ks * 32 + ATILE);
            }
        }

        const uint32_t kb = sb + AQ + (kt & 1) * ASTAGE;

        // ---- S = Q K^T (16 n8 accumulators over 128 keys) -------------------
        float SS[16][4];
#pragma unroll
        for (int ni = 0; ni < 16; ni++)
#pragma unroll
            for (int q = 0; q < 4; q++) SS[ni][q] = 0.f;

#pragma unroll
        for (int ks = 0; ks < 4; ks++) {
#pragma unroll
            for (int nip = 0; nip < 8; nip++) {
                uint32_t bhr[4], blr[4];
                const uint32_t a = kb + (nip * 16 + kRow) * AKSTR + ks * 32 + kColB;
                ldsm_x4(bhr, a);
                ldsm_x4(blr, a + ATILE);
                mma_bf16(SS[2 * nip],     Qh[ks], bhr);
                mma_bf16(SS[2 * nip],     Qh[ks], blr);
                mma_bf16(SS[2 * nip],     Ql[ks], bhr);
                mma_bf16(SS[2 * nip + 1], Qh[ks], bhr + 2);
                mma_bf16(SS[2 * nip + 1], Qh[ks], blr + 2);
                mma_bf16(SS[2 * nip + 1], Ql[ks], bhr + 2);
            }
        }

        // ---- online softmax (rows g and g+8, reductions within quad) --------
#pragma unroll
        for (int ni = 0; ni < 16; ni++)
#pragma unroll
            for (int q = 0; q < 4; q++) SS[ni][q] *= 0.125f;

        if (kt == NTIL - 1) {
            const int kb0 = kt * 128 + 2 * t;
#pragma unroll
            for (int ni = 0; ni < 16; ni++) {
                const int kk = kb0 + ni * 8;
                if (kk     >= Ss) { SS[ni][0] = -1e30f; SS[ni][2] = -1e30f; }
                if (kk + 1 >= Ss) { SS[ni][1] = -1e30f; SS[ni][3] = -1e30f; }
            }
        }

        float rm0 = -1e30f, rm1 = -1e30f;
#pragma unroll
        for (int ni = 0; ni < 16; ni++) {
            rm0 = fmaxf(rm0, fmaxf(SS[ni][0], SS[ni][1]));
            rm1 = fmaxf(rm1, fmaxf(SS[ni][2], SS[ni][3]));
        }
        rm0 = fmaxf(rm0, __shfl_xor_sync(0xffffffffu, rm0, 1));
        rm0 = fmaxf(rm0, __shfl_xor_sync(0xffffffffu, rm0, 2));
        rm1 = fmaxf(rm1, __shfl_xor_sync(0xffffffffu, rm1, 1));
        rm1 = fmaxf(rm1, __shfl_xor_sync(0xffffffffu, rm1, 2));

        const float mn0 = fmaxf(m0_, rm0);
        const float mn1 = fmaxf(m1_, rm1);
        const float a0  = __expf(m0_ - mn0);
        const float a1  = __expf(m1_ - mn1);
        m0_ = mn0; m1_ = mn1;

        float sum0 = 0.f, sum1 = 0.f;
#pragma unroll
        for (int ni = 0; ni < 16; ni++) {
            SS[ni][0] = __expf(SS[ni][0] - mn0);
            SS[ni][1] = __expf(SS[ni][1] - mn0);
            SS[ni][2] = __expf(SS[ni][2] - mn1);
            SS[ni][3] = __expf(SS[ni][3] - mn1);
            sum0 += SS[ni][0] + SS[ni][1];
            sum1 += SS[ni][2] + SS[ni][3];
        }
        sum0 += __shfl_xor_sync(0xffffffffu, sum0, 1);
        sum0 += __shfl_xor_sync(0xffffffffu, sum0, 2);
        sum1 += __shfl_xor_sync(0xffffffffu, sum1, 1);
        sum1 += __shfl_xor_sync(0xffffffffu, sum1, 2);
        l0_ = l0_ * a0 + sum0;
        l1_ = l1_ * a1 + sum1;

#pragma unroll
        for (int ni = 0; ni < 8; ni++) {
            O[ni][0] *= a0; O[ni][1] *= a0;
            O[ni][2] *= a1; O[ni][3] *= a1;
        }

        // ---- O += P V  (P hi/lo packed register-to-register) ----------------
        const uint32_t vb = kb + 2 * ATILE;
#pragma unroll
        for (int j = 0; j < 8; j++) {
            uint32_t ph[4], pl[4];
            {
                const float c0 = SS[2 * j][0],     c1 = SS[2 * j][1];
                const float c2 = SS[2 * j][2],     c3 = SS[2 * j][3];
                const float d0 = SS[2 * j + 1][0], d1 = SS[2 * j + 1][1];
                const float d2 = SS[2 * j + 1][2], d3 = SS[2 * j + 1][3];
                ph[0] = pack_bf16x2(c0, c1); ph[1] = pack_bf16x2(c2, c3);
                ph[2] = pack_bf16x2(d0, d1); ph[3] = pack_bf16x2(d2, d3);
                __nv_bfloat162 h0 = *(__nv_bfloat162*)&ph[0];
                __nv_bfloat162 h1 = *(__nv_bfloat162*)&ph[1];
                __nv_bfloat162 h2 = *(__nv_bfloat162*)&ph[2];
                __nv_bfloat162 h3 = *(__nv_bfloat162*)&ph[3];
                float2 f0 = __bfloat1622float2(h0), f1 = __bfloat1622float2(h1);
                float2 f2 = __bfloat1622float2(h2), f3 = __bfloat1622float2(h3);
                pl[0] = pack_bf16x2(c0 - f0.x, c1 - f0.y);
                pl[1] = pack_bf16x2(c2 - f1.x, c3 - f1.y);
                pl[2] = pack_bf16x2(d0 - f2.x, d1 - f2.y);
                pl[3] = pack_bf16x2(d2 - f3.x, d3 - f3.y);
            }
#pragma unroll
            for (int nip = 0; nip < 4; nip++) {
                uint32_t bhr[4], blr[4];
                const uint32_t a = vb + (j * 16 + vRow) * AKSTR + nip * 32 + vColB;
                ldsm_x4t(bhr, a);
                ldsm_x4t(blr, a + ATILE);
                mma_bf16(O[2 * nip],     ph, bhr);
                mma_bf16(O[2 * nip],     ph, blr);
                mma_bf16(O[2 * nip],     pl, bhr);
                mma_bf16(O[2 * nip + 1], ph, bhr + 2);
                mma_bf16(O[2 * nip + 1], ph, blr + 2);
                mma_bf16(O[2 * nip + 1], pl, bhr + 2);
            }
        }
        __syncthreads();
    }

    // ---- epilogue -----------------------------------------------------------
    const int r0 = qt * 128 + wid * 16 + g;
    const int r1 = r0 + 8;
    const float inv0 = 1.f / l0_;
    const float inv1 = 1.f / l1_;
#pragma unroll
    for (int ni = 0; ni < 8; ni++) {
        const int d = h * HDim + ni * 8 + 2 * t;
        if (r0 < Ss)
            *(float2*)&Out[((size_t)b * Ss + r0) * Dd + d] =
                make_float2(O[ni][0] * inv0, O[ni][1] * inv0);
        if (r1 < Ss)
            *(float2*)&Out[((size_t)b * Ss + r1) * Dd + d] =
                make_float2(O[ni][2] * inv1, O[ni][3] * inv1);
    }
}

// ---------------------------------------------------------------------------
extern "C" void kernel_launch(void* const* d_in, const int* in_sizes, int n_in,
                              void* d_out, int out_size)
{
    const float* X  = (const float*)d_in[0];
    const float* Wq = (const float*)d_in[1];
    const float* bq = (const float*)d_in[2];
    const float* Wk = (const float*)d_in[3];
    const float* bk = (const float*)d_in[4];
    const float* Wv = (const float*)d_in[5];
    const float* bv = (const float*)d_in[6];
    float* out = (float*)d_out;

    const int nX4 = Mtot * Dd / 4;
    const int nW4 = Dd * Dd / 4;
    split_kernel<<<(nX4 + 255) / 256, 256>>>(X, 0, nX4);
    split_kernel<<<(nW4 + 255) / 256, 256>>>(Wq, 1, nW4);
    split_kernel<<<(nW4 + 255) / 256, 256>>>(Wk, 2, nW4);
    split_kernel<<<(nW4 + 255) / 256, 256>>>(Wv, 3, nW4);

    cudaFuncSetAttribute(qkv_gemm_mma, cudaFuncAttributeMaxDynamicSharedMemorySize,
                         GEMM_SMEM);
    dim3 gg(Dd / 128, (Mtot + 127) / 128, 3);
    qkv_gemm_mma<<<gg, 256, GEMM_SMEM>>>(bq, bk, bv);

    cudaFuncSetAttribute(attn_mma, cudaFuncAttributeMaxDynamicSharedMemorySize,
                         ATTN_SMEM);
    dim3 g2((Ss + 127) / 128, Hh, Bb);          // (11, 16, 8)
    attn_mma<<<g2, 256, ATTN_SMEM>>>(out);
}

// round 11
// speedup vs baseline: 3.9185x; 1.3912x over previous
#include <cuda_runtime.h>
#include <cuda_fp16.h>
#include <math.h>
#include <stdint.h>

// Problem constants
#define Bb   8
#define Ss   1370
#define Dd   1024
#define Hh   16
#define HDim 64
#define Mtot (Bb * Ss)          // 10960

// ---------------------------------------------------------------------------
// Static device scratch (allocation-free)
// ---------------------------------------------------------------------------
__device__ __half g_Xh[Mtot * Dd];      // X hi (fp16)
__device__ __half g_Xl[Mtot * Dd];      // X lo (fp16 residual)
__device__ __half g_W [3 * Dd * Dd];    // Wq|Wk|Wv single fp16

// head-major [B,H,S,64]
__device__ __half g_Qh[Bb * Hh * Ss * HDim];
__device__ __half g_Ql[Bb * Hh * Ss * HDim];
__device__ __half g_K [Bb * Hh * Ss * HDim];   // single fp16
__device__ __half g_Vh[Bb * Hh * Ss * HDim];
__device__ __half g_Vl[Bb * Hh * Ss * HDim];

// ---------------------------------------------------------------------------
// PTX helpers — arch-generic only (no tcgen05: harness ptx target is bare 103)
// ---------------------------------------------------------------------------
__device__ __forceinline__ uint32_t smem_u32(const void* p) {
    uint32_t a;
    asm("{ .reg .u64 t; cvta.to.shared.u64 t, %1; cvt.u32.u64 %0, t; }"
        : "=r"(a) : "l"(p));
    return a;
}
__device__ __forceinline__ void cp16(uint32_t d, const void* s, uint32_t sz) {
    asm volatile("cp.async.cg.shared.global [%0], [%1], 16, %2;"
                 :: "r"(d), "l"(s), "r"(sz) : "memory");
}
__device__ __forceinline__ void cp_commit() {
    asm volatile("cp.async.commit_group;" ::: "memory");
}
__device__ __forceinline__ void cp_wait1() {
    asm volatile("cp.async.wait_group 1;" ::: "memory");
}
__device__ __forceinline__ void cp_wait0() {
    asm volatile("cp.async.wait_group 0;" ::: "memory");
}
__device__ __forceinline__ void ldsm_x4(uint32_t* r, uint32_t addr) {
    asm volatile("ldmatrix.sync.aligned.m8n8.x4.shared.b16 {%0,%1,%2,%3}, [%4];"
                 : "=r"(r[0]), "=r"(r[1]), "=r"(r[2]), "=r"(r[3]) : "r"(addr));
}
__device__ __forceinline__ void ldsm_x4t(uint32_t* r, uint32_t addr) {
    asm volatile("ldmatrix.sync.aligned.m8n8.x4.trans.shared.b16 {%0,%1,%2,%3}, [%4];"
                 : "=r"(r[0]), "=r"(r[1]), "=r"(r[2]), "=r"(r[3]) : "r"(addr));
}
__device__ __forceinline__ void ldsm_x2(uint32_t* r, uint32_t addr) {
    asm volatile("ldmatrix.sync.aligned.m8n8.x2.shared.b16 {%0,%1}, [%2];"
                 : "=r"(r[0]), "=r"(r[1]) : "r"(addr));
}
__device__ __forceinline__ void mma_f16(float* c, const uint32_t* a, const uint32_t* b) {
    asm volatile(
        "mma.sync.aligned.m16n8k16.row.col.f32.f16.f16.f32 "
        "{%0,%1,%2,%3}, {%4,%5,%6,%7}, {%8,%9}, {%0,%1,%2,%3};"
        : "+f"(c[0]), "+f"(c[1]), "+f"(c[2]), "+f"(c[3])
        : "r"(a[0]), "r"(a[1]), "r"(a[2]), "r"(a[3]), "r"(b[0]), "r"(b[1]));
}
__device__ __forceinline__ uint32_t pack_h2(float x, float y) {
    __half2 h = __floats2half2_rn(x, y);
    return *reinterpret_cast<uint32_t*>(&h);
}

// ---------------------------------------------------------------------------
// fp32 -> fp16.  mode 0: X -> hi + lo residual.  modes 1..3: W -> single fp16.
// ---------------------------------------------------------------------------
__global__ void split_kernel(const float* __restrict__ src, int mode, int n4)
{
    int i = blockIdx.x * blockDim.x + threadIdx.x;
    if (i >= n4) return;
    float4 v = ((const float4*)src)[i];
    if (mode == 0) {
        __half2 h01 = __floats2half2_rn(v.x, v.y);
        __half2 h23 = __floats2half2_rn(v.z, v.w);
        float2 f01 = __half22float2(h01);
        float2 f23 = __half22float2(h23);
        __half2 l01 = __floats2half2_rn(v.x - f01.x, v.y - f01.y);
        __half2 l23 = __floats2half2_rn(v.z - f23.x, v.w - f23.y);
        ((__half2*)g_Xh)[2 * i]     = h01;
        ((__half2*)g_Xh)[2 * i + 1] = h23;
        ((__half2*)g_Xl)[2 * i]     = l01;
        ((__half2*)g_Xl)[2 * i + 1] = l23;
    } else {
        __half* w = g_W + (size_t)(mode - 1) * Dd * Dd;
        ((__half2*)w)[2 * i]     = __floats2half2_rn(v.x, v.y);
        ((__half2*)w)[2 * i + 1] = __floats2half2_rn(v.z, v.w);
    }
}

// ---------------------------------------------------------------------------
// QKV GEMM via mma.sync fp16, 2-pass split: (Xh + Xl) @ W^T.
// CTA 128x128, BK=32, 8 warps (2Mx4N), warp 64x32.
// smem per stage: Ah | Al | B (3 tiles), row stride 80B.
// Epilogue: +bias; Q,V -> fp16 hi/lo head-major; K -> single fp16.
// ---------------------------------------------------------------------------
#define ROWB     80
#define TILE_B   (128 * ROWB)             // 10240
#define STAGE_B  (3 * TILE_B)             // 30720
#define GEMM_SMEM (2 * STAGE_B)           // 61440
#define NCHUNK   (Dd / 32)                // 32

__global__ __launch_bounds__(256, 1) void qkv_gemm_mma(
    const float* __restrict__ bq, const float* __restrict__ bk,
    const float* __restrict__ bv)
{
    extern __shared__ char smc[];
    const uint32_t sb = smem_u32(smc);
    const int tid = threadIdx.x;
    const int wid = tid >> 5;
    const int lid = tid & 31;

    const int nt = blockIdx.x;
    const int mt = blockIdx.y;
    const int z  = blockIdx.z;
    const int row0 = mt * 128;
    const int col0 = nt * 128;

    const __half* __restrict__ Wz = g_W + (size_t)z * Dd * Dd;
    const float* __restrict__ bias = (z == 0) ? bq : (z == 1) ? bk : bv;
    __half* __restrict__ OutH = (z == 0) ? g_Qh : (z == 1) ? g_K : g_Vh;
    __half* __restrict__ OutL = (z == 0) ? g_Ql : (z == 2) ? g_Vl : g_Ql; // unused for z==1

    const int wm = wid & 1;
    const int wn = wid >> 1;
    const int aRow = lid & 15;
    const int aKof = (lid >> 4) * 8;
    const int bRow = lid & 7;
    const int bKof = ((lid >> 3) & 1) * 8;

    float acc[4][4][4];
#pragma unroll
    for (int mi = 0; mi < 4; mi++)
#pragma unroll
        for (int ni = 0; ni < 4; ni++)
#pragma unroll
            for (int q = 0; q < 4; q++) acc[mi][ni][q] = 0.f;

    auto load_chunk = [&](int c, int s) {
        const uint32_t stg = sb + s * STAGE_B;
        const int k0 = c * 32;
#pragma unroll
        for (int i = 0; i < 6; i++) {
            const int v    = tid + i * 256;
            const int tile = v >> 9;                 // 0=Ah 1=Al 2=B
            const int r    = (v >> 2) & 127;
            const int u    = v & 3;
            const uint32_t doff = stg + tile * TILE_B + r * ROWB + u * 16;
            const __half* src;
            uint32_t sz = 16;
            if (tile < 2) {
                const int m = row0 + r;
                const __half* base = (tile == 0) ? g_Xh : g_Xl;
                src = base + (size_t)((m < Mtot) ? m : 0) * Dd + k0 + u * 8;
                if (m >= Mtot) sz = 0;
            } else {
                src = Wz + (size_t)(col0 + r) * Dd + k0 + u * 8;
            }
            cp16(doff, src, sz);
        }
        cp_commit();
    };

    load_chunk(0, 0);

    for (int c = 0; c < NCHUNK; c++) {
        if (c + 1 < NCHUNK) { load_chunk(c + 1, (c + 1) & 1); cp_wait1(); }
        else                { cp_wait0(); }
        __syncthreads();

        const uint32_t stg = sb + (c & 1) * STAGE_B;
        const uint32_t aHi = stg + (wm * 64 + aRow) * ROWB + aKof * 2;
        const uint32_t bB  = stg + 2 * TILE_B + (wn * 32 + bRow) * ROWB + bKof * 2;

#pragma unroll
        for (int kk = 0; kk < 32; kk += 16) {
            uint32_t Ah[4][4], Al[4][4], Bf[4][2];
#pragma unroll
            for (int mi = 0; mi < 4; mi++) {
                const uint32_t a = aHi + mi * (16 * ROWB) + kk * 2;
                ldsm_x4(Ah[mi], a);
                ldsm_x4(Al[mi], a + TILE_B);
            }
#pragma unroll
            for (int ni = 0; ni < 4; ni++)
                ldsm_x2(Bf[ni], bB + ni * (8 * ROWB) + kk * 2);
#pragma unroll
            for (int mi = 0; mi < 4; mi++)
#pragma unroll
                for (int ni = 0; ni < 4; ni++) {
                    mma_f16(acc[mi][ni], Ah[mi], Bf[ni]);
                    mma_f16(acc[mi][ni], Al[mi], Bf[ni]);
                }
        }
        __syncthreads();
    }

    // epilogue: bias; Q/V -> hi/lo fp16, K -> single fp16; head-major scatter
    const int gq = lid >> 2;
    const int t  = lid & 3;
#pragma unroll
    for (int mi = 0; mi < 4; mi++) {
        const int m0 = row0 + wm * 64 + mi * 16 + gq;
#pragma unroll
        for (int half_ = 0; half_ < 2; half_++) {
            const int m = m0 + half_ * 8;
            if (m >= Mtot) continue;
            const int bix  = m / Ss;
            const int srow = m - bix * Ss;
#pragma unroll
            for (int ni = 0; ni < 4; ni++) {
                const int n = col0 + wn * 32 + ni * 8 + t * 2;
                const int h = n >> 6;
                const int d = n & 63;
                const float vx = acc[mi][ni][half_ * 2 + 0] + __ldg(bias + n);
                const float vy = acc[mi][ni][half_ * 2 + 1] + __ldg(bias + n + 1);
                const size_t idx = (((size_t)(bix * Hh + h) * Ss + srow) << 6) + d;
                __half2 h2 = __floats2half2_rn(vx, vy);
                *(uint32_t*)&OutH[idx] = *(uint32_t*)&h2;
                if (z != 1) {
                    float2 f = __half22float2(h2);
                    __half2 l2 = __floats2half2_rn(vx - f.x, vy - f.y);
                    *(uint32_t*)&OutL[idx] = *(uint32_t*)&l2;
                }
            }
        }
    }
}

// ---------------------------------------------------------------------------
// Flash attention via mma.sync fp16, 2-pass split.
// CTA = 128 Q rows of one (b,h); 8 warps x 16 rows; 128-key tiles.
// smem: Qh|Ql (2 tiles) + 2 stages x (K|Vh|Vl). Row stride 144B.
// Scores: (Qh+Ql)·K ; PV: P_fp16·(Vh+Vl).
// ---------------------------------------------------------------------------
#define AKSTR   144
#define ATILE   (128 * AKSTR)            // 18432
#define ASTAGE  (3 * ATILE)              // 55296
#define AQ2     (2 * ATILE)              // 36864
#define ATTN_SMEM (AQ2 + 2 * ASTAGE)     // 147456
#define NTIL    ((Ss + 127) / 128)       // 11

__global__ __launch_bounds__(256, 1) void attn_mma(float* __restrict__ Out)
{
    extern __shared__ char smc[];
    const uint32_t sb = smem_u32(smc);
    const int tid = threadIdx.x;
    const int wid = tid >> 5;
    const int lid = tid & 31;
    const int qt  = blockIdx.x;
    const int h   = blockIdx.y;
    const int b   = blockIdx.z;

    const size_t bh = (size_t)(b * Hh + h) * Ss * HDim;

    auto load_q = [&]() {
#pragma unroll
        for (int i = 0; i < 8; i++) {
            const int u    = tid + i * 256;
            const int tile = u >> 10;           // 0 = Qh, 1 = Ql
            const int r    = (u >> 3) & 127;
            const int uc   = u & 7;
            const int row  = qt * 128 + r;
            const bool v   = (row < Ss);
            const __half* gp =
                (tile ? g_Ql : g_Qh) + bh + (size_t)(v ? row : 0) * HDim + uc * 8;
            cp16(sb + tile * ATILE + r * AKSTR + uc * 16, gp, v ? 16u : 0u);
        }
    };
    auto load_kv = [&](int kt, int s) {
        const uint32_t base = sb + AQ2 + s * ASTAGE;
#pragma unroll
        for (int i = 0; i < 12; i++) {
            const int u    = tid + i * 256;
            const int tile = u >> 10;           // 0=K 1=Vh 2=Vl
            const int r    = (u >> 3) & 127;
            const int uc   = u & 7;
            const int key  = kt * 128 + r;
            const bool v   = (key < Ss);
            const __half* gp =
                (tile == 0 ? g_K : tile == 1 ? g_Vh : g_Vl)
                + bh + (size_t)(v ? key : 0) * HDim + uc * 8;
            cp16(base + tile * ATILE + r * AKSTR + uc * 16, gp, v ? 16u : 0u);
        }
    };

    load_q();
    load_kv(0, 0);
    cp_commit();

    const int t  = lid & 3;
    const int gq = lid >> 2;
    const int kRow  = (lid & 7) + ((lid >> 4) & 1) * 8;
    const int kColB = ((lid >> 3) & 1) * 16;
    const int vRow  = (lid & 7) + ((lid >> 3) & 1) * 8;
    const int vColB = ((lid >> 4) & 1) * 16;

    float m0_ = -1e30f, m1_ = -1e30f, l0_ = 0.f, l1_ = 0.f;
    float O[8][4];
#pragma unroll
    for (int ni = 0; ni < 8; ni++)
#pragma unroll
        for (int q = 0; q < 4; q++) O[ni][q] = 0.f;

    uint32_t Qh[4][4], Ql[4][4];

    for (int kt = 0; kt < NTIL; kt++) {
        if (kt + 1 < NTIL) { load_kv(kt + 1, (kt + 1) & 1); cp_commit(); cp_wait1(); }
        else               { cp_wait0(); }
        __syncthreads();

        if (kt == 0) {
            const uint32_t qb = sb + (wid * 16 + vRow) * AKSTR + vColB;
#pragma unroll
            for (int ks = 0; ks < 4; ks++) {
                ldsm_x4(Qh[ks], qb + ks * 32);
                ldsm_x4(Ql[ks], qb + ks * 32 + ATILE);
            }
        }

        const uint32_t kb = sb + AQ2 + (kt & 1) * ASTAGE;

        // ---- S = Q K^T : 2-pass (Qh + Ql) x K -------------------------------
        float SS[16][4];
#pragma unroll
        for (int ni = 0; ni < 16; ni++)
#pragma unroll
            for (int q = 0; q < 4; q++) SS[ni][q] = 0.f;

#pragma unroll
        for (int ks = 0; ks < 4; ks++) {
#pragma unroll
            for (int nip = 0; nip < 8; nip++) {
                uint32_t kf[4];
                ldsm_x4(kf, kb + (nip * 16 + kRow) * AKSTR + ks * 32 + kColB);
                mma_f16(SS[2 * nip],     Qh[ks], kf);
                mma_f16(SS[2 * nip],     Ql[ks], kf);
                mma_f16(SS[2 * nip + 1], Qh[ks], kf + 2);
                mma_f16(SS[2 * nip + 1], Ql[ks], kf + 2);
            }
        }

        // ---- online softmax --------------------------------------------------
#pragma unroll
        for (int ni = 0; ni < 16; ni++)
#pragma unroll
            for (int q = 0; q < 4; q++) SS[ni][q] *= 0.125f;

        if (kt == NTIL - 1) {
            const int kb0 = kt * 128 + 2 * t;
#pragma unroll
            for (int ni = 0; ni < 16; ni++) {
                const int kk = kb0 + ni * 8;
                if (kk     >= Ss) { SS[ni][0] = -1e30f; SS[ni][2] = -1e30f; }
                if (kk + 1 >= Ss) { SS[ni][1] = -1e30f; SS[ni][3] = -1e30f; }
            }
        }

        float rm0 = -1e30f, rm1 = -1e30f;
#pragma unroll
        for (int ni = 0; ni < 16; ni++) {
            rm0 = fmaxf(rm0, fmaxf(SS[ni][0], SS[ni][1]));
            rm1 = fmaxf(rm1, fmaxf(SS[ni][2], SS[ni][3]));
        }
        rm0 = fmaxf(rm0, __shfl_xor_sync(0xffffffffu, rm0, 1));
        rm0 = fmaxf(rm0, __shfl_xor_sync(0xffffffffu, rm0, 2));
        rm1 = fmaxf(rm1, __shfl_xor_sync(0xffffffffu, rm1, 1));
        rm1 = fmaxf(rm1, __shfl_xor_sync(0xffffffffu, rm1, 2));

        const float mn0 = fmaxf(m0_, rm0);
        const float mn1 = fmaxf(m1_, rm1);
        const float a0  = __expf(m0_ - mn0);
        const float a1  = __expf(m1_ - mn1);
        m0_ = mn0; m1_ = mn1;

        float sum0 = 0.f, sum1 = 0.f;
#pragma unroll
        for (int ni = 0; ni < 16; ni++) {
            SS[ni][0] = __expf(SS[ni][0] - mn0);
            SS[ni][1] = __expf(SS[ni][1] - mn0);
            SS[ni][2] = __expf(SS[ni][2] - mn1);
            SS[ni][3] = __expf(SS[ni][3] - mn1);
            sum0 += SS[ni][0] + SS[ni][1];
            sum1 += SS[ni][2] + SS[ni][3];
        }
        sum0 += __shfl_xor_sync(0xffffffffu, sum0, 1);
        sum0 += __shfl_xor_sync(0xffffffffu, sum0, 2);
        sum1 += __shfl_xor_sync(0xffffffffu, sum1, 1);
        sum1 += __shfl_xor_sync(0xffffffffu, sum1, 2);
        l0_ = l0_ * a0 + sum0;
        l1_ = l1_ * a1 + sum1;

#pragma unroll
        for (int ni = 0; ni < 8; ni++) {
            O[ni][0] *= a0; O[ni][1] *= a0;
            O[ni][2] *= a1; O[ni][3] *= a1;
        }

        // ---- O += P V : P fp16 (reg-to-reg pack), 2-pass over V hi/lo --------
        const uint32_t vb = kb + ATILE;
#pragma unroll
        for (int j = 0; j < 8; j++) {
            uint32_t ph[4];
            ph[0] = pack_h2(SS[2 * j][0],     SS[2 * j][1]);
            ph[1] = pack_h2(SS[2 * j][2],     SS[2 * j][3]);
            ph[2] = pack_h2(SS[2 * j + 1][0], SS[2 * j + 1][1]);
            ph[3] = pack_h2(SS[2 * j + 1][2], SS[2 * j + 1][3]);
#pragma unroll
            for (int nip = 0; nip < 4; nip++) {
                uint32_t vh[4], vl[4];
                const uint32_t a = vb + (j * 16 + vRow) * AKSTR + nip * 32 + vColB;
                ldsm_x4t(vh, a);
                ldsm_x4t(vl, a + ATILE);
                mma_f16(O[2 * nip],     ph, vh);
                mma_f16(O[2 * nip],     ph, vl);
                mma_f16(O[2 * nip + 1], ph, vh + 2);
                mma_f16(O[2 * nip + 1], ph, vl + 2);
            }
        }
        __syncthreads();
    }

    // ---- epilogue -----------------------------------------------------------
    const int r0 = qt * 128 + wid * 16 + gq;
    const int r1 = r0 + 8;
    const float inv0 = 1.f / l0_;
    const float inv1 = 1.f / l1_;
#pragma unroll
    for (int ni = 0; ni < 8; ni++) {
        const int d = h * HDim + ni * 8 + 2 * t;
        if (r0 < Ss)
            *(float2*)&Out[((size_t)b * Ss + r0) * Dd + d] =
                make_float2(O[ni][0] * inv0, O[ni][1] * inv0);
        if (r1 < Ss)
            *(float2*)&Out[((size_t)b * Ss + r1) * Dd + d] =
                make_float2(O[ni][2] * inv1, O[ni][3] * inv1);
    }
}

// ---------------------------------------------------------------------------
extern "C" void kernel_launch(void* const* d_in, const int* in_sizes, int n_in,
                              void* d_out, int out_size)
{
    const float* X  = (const float*)d_in[0];
    const float* Wq = (const float*)d_in[1];
    const float* bq = (const float*)d_in[2];
    const float* Wk = (const float*)d_in[3];
    const float* bk = (const float*)d_in[4];
    const float* Wv = (const float*)d_in[5];
    const float* bv = (const float*)d_in[6];
    float* out = (float*)d_out;

    const int nX4 = Mtot * Dd / 4;
    const int nW4 = Dd * Dd / 4;
    split_kernel<<<(nX4 + 255) / 256, 256>>>(X, 0, nX4);
    split_kernel<<<(nW4 + 255) / 256, 256>>>(Wq, 1, nW4);
    split_kernel<<<(nW4 + 255) / 256, 256>>>(Wk, 2, nW4);
    split_kernel<<<(nW4 + 255) / 256, 256>>>(Wv, 3, nW4);

    cudaFuncSetAttribute(qkv_gemm_mma, cudaFuncAttributeMaxDynamicSharedMemorySize,
                         GEMM_SMEM);
    dim3 gg(Dd / 128, (Mtot + 127) / 128, 3);
    qkv_gemm_mma<<<gg, 256, GEMM_SMEM>>>(bq, bk, bv);

    cudaFuncSetAttribute(attn_mma, cudaFuncAttributeMaxDynamicSharedMemorySize,
                         ATTN_SMEM);
    dim3 g2((Ss + 127) / 128, Hh, Bb);          // (11, 16, 8)
    attn_mma<<<g2, 256, ATTN_SMEM>>>(out);
}

// round 14
// speedup vs baseline: 4.7530x; 1.2130x over previous
#include <cuda_runtime.h>
#include <cuda_fp16.h>
#include <math.h>
#include <stdint.h>

// Problem constants
#define Bb   8
#define Ss   1370
#define Dd   1024
#define Hh   16
#define HDim 64
#define Mtot (Bb * Ss)          // 10960

// ---------------------------------------------------------------------------
// Static device scratch (allocation-free)
// ---------------------------------------------------------------------------
__device__ __half g_Xh[Mtot * Dd];      // X hi (fp16)
__device__ __half g_Xl[Mtot * Dd];      // X lo (fp16 residual)
__device__ __half g_W [3 * Dd * Dd];    // Wq|Wk|Wv single fp16

// head-major [B,H,S,64], all single fp16
__device__ __half g_Q[Bb * Hh * Ss * HDim];
__device__ __half g_K[Bb * Hh * Ss * HDim];
__device__ __half g_V[Bb * Hh * Ss * HDim];

// ---------------------------------------------------------------------------
// PTX helpers — arch-generic only (no tcgen05: harness ptx target is bare 103)
// ---------------------------------------------------------------------------
__device__ __forceinline__ uint32_t smem_u32(const void* p) {
    uint32_t a;
    asm("{ .reg .u64 t; cvta.to.shared.u64 t, %1; cvt.u32.u64 %0, t; }"
        : "=r"(a) : "l"(p));
    return a;
}
__device__ __forceinline__ void cp16(uint32_t d, const void* s, uint32_t sz) {
    asm volatile("cp.async.cg.shared.global [%0], [%1], 16, %2;"
                 :: "r"(d), "l"(s), "r"(sz) : "memory");
}
__device__ __forceinline__ void cp_commit() {
    asm volatile("cp.async.commit_group;" ::: "memory");
}
__device__ __forceinline__ void cp_wait1() {
    asm volatile("cp.async.wait_group 1;" ::: "memory");
}
__device__ __forceinline__ void cp_wait0() {
    asm volatile("cp.async.wait_group 0;" ::: "memory");
}
__device__ __forceinline__ void ldsm_x4(uint32_t* r, uint32_t addr) {
    asm volatile("ldmatrix.sync.aligned.m8n8.x4.shared.b16 {%0,%1,%2,%3}, [%4];"
                 : "=r"(r[0]), "=r"(r[1]), "=r"(r[2]), "=r"(r[3]) : "r"(addr));
}
__device__ __forceinline__ void ldsm_x4t(uint32_t* r, uint32_t addr) {
    asm volatile("ldmatrix.sync.aligned.m8n8.x4.trans.shared.b16 {%0,%1,%2,%3}, [%4];"
                 : "=r"(r[0]), "=r"(r[1]), "=r"(r[2]), "=r"(r[3]) : "r"(addr));
}
__device__ __forceinline__ void ldsm_x2(uint32_t* r, uint32_t addr) {
    asm volatile("ldmatrix.sync.aligned.m8n8.x2.shared.b16 {%0,%1}, [%2];"
                 : "=r"(r[0]), "=r"(r[1]) : "r"(addr));
}
__device__ __forceinline__ void mma_f16(float* c, const uint32_t* a, const uint32_t* b) {
    asm volatile(
        "mma.sync.aligned.m16n8k16.row.col.f32.f16.f16.f32 "
        "{%0,%1,%2,%3}, {%4,%5,%6,%7}, {%8,%9}, {%0,%1,%2,%3};"
        : "+f"(c[0]), "+f"(c[1]), "+f"(c[2]), "+f"(c[3])
        : "r"(a[0]), "r"(a[1]), "r"(a[2]), "r"(a[3]), "r"(b[0]), "r"(b[1]));
}
__device__ __forceinline__ uint32_t pack_h2(float x, float y) {
    __half2 h = __floats2half2_rn(x, y);
    return *reinterpret_cast<uint32_t*>(&h);
}

// ---------------------------------------------------------------------------
// fp32 -> fp16.  mode 0: X -> hi + lo residual.  modes 1..3: W -> single fp16.
// ---------------------------------------------------------------------------
__global__ void split_kernel(const float* __restrict__ src, int mode, int n4)
{
    int i = blockIdx.x * blockDim.x + threadIdx.x;
    if (i >= n4) return;
    float4 v = ((const float4*)src)[i];
    if (mode == 0) {
        __half2 h01 = __floats2half2_rn(v.x, v.y);
        __half2 h23 = __floats2half2_rn(v.z, v.w);
        float2 f01 = __half22float2(h01);
        float2 f23 = __half22float2(h23);
        __half2 l01 = __floats2half2_rn(v.x - f01.x, v.y - f01.y);
        __half2 l23 = __floats2half2_rn(v.z - f23.x, v.w - f23.y);
        ((__half2*)g_Xh)[2 * i]     = h01;
        ((__half2*)g_Xh)[2 * i + 1] = h23;
        ((__half2*)g_Xl)[2 * i]     = l01;
        ((__half2*)g_Xl)[2 * i + 1] = l23;
    } else {
        __half* w = g_W + (size_t)(mode - 1) * Dd * Dd;
        ((__half2*)w)[2 * i]     = __floats2half2_rn(v.x, v.y);
        ((__half2*)w)[2 * i + 1] = __floats2half2_rn(v.z, v.w);
    }
}

// ---------------------------------------------------------------------------
// QKV GEMM via mma.sync fp16.
// Q (z==0): 2-pass (Xh+Xl)@W^T.  K,V (z==1,2): 1-pass Xh@W^T.
// CTA 128x128, BK=32, 8 warps (2Mx4N), warp 64x32.
// smem per stage: Ah | Al | B (3 tiles), row stride 80B.
// Epilogue: +bias; single fp16 head-major output.
// ---------------------------------------------------------------------------
#define ROWB     80
#define TILE_B   (128 * ROWB)             // 10240
#define STAGE_B  (3 * TILE_B)             // 30720
#define GEMM_SMEM (2 * STAGE_B)           // 61440
#define NCHUNK   (Dd / 32)                // 32

__global__ __launch_bounds__(256, 1) void qkv_gemm_mma(
    const float* __restrict__ bq, const float* __restrict__ bk,
    const float* __restrict__ bv)
{
    extern __shared__ char smc[];
    const uint32_t sb = smem_u32(smc);
    const int tid = threadIdx.x;
    const int wid = tid >> 5;
    const int lid = tid & 31;

    const int nt = blockIdx.x;
    const int mt = blockIdx.y;
    const int z  = blockIdx.z;
    const int row0 = mt * 128;
    const int col0 = nt * 128;
    const bool twoPass = (z == 0);

    const __half* __restrict__ Wz = g_W + (size_t)z * Dd * Dd;
    const float* __restrict__ bias = (z == 0) ? bq : (z == 1) ? bk : bv;
    __half* __restrict__ OutH = (z == 0) ? g_Q : (z == 1) ? g_K : g_V;

    const int wm = wid & 1;
    const int wn = wid >> 1;
    const int aRow = lid & 15;
    const int aKof = (lid >> 4) * 8;
    const int bRow = lid & 7;
    const int bKof = ((lid >> 3) & 1) * 8;

    float acc[4][4][4];
#pragma unroll
    for (int mi = 0; mi < 4; mi++)
#pragma unroll
        for (int ni = 0; ni < 4; ni++)
#pragma unroll
            for (int q = 0; q < 4; q++) acc[mi][ni][q] = 0.f;

    auto load_chunk = [&](int c, int s) {
        const uint32_t stg = sb + s * STAGE_B;
        const int k0 = c * 32;
        if (twoPass) {
#pragma unroll
            for (int i = 0; i < 6; i++) {
                const int v    = tid + i * 256;
                const int tile = v >> 9;                 // 0=Ah 1=Al 2=B
                const int r    = (v >> 2) & 127;
                const int u    = v & 3;
                const uint32_t doff = stg + tile * TILE_B + r * ROWB + u * 16;
                const __half* src;
                uint32_t sz = 16;
                if (tile < 2) {
                    const int m = row0 + r;
                    const __half* base = (tile == 0) ? g_Xh : g_Xl;
                    src = base + (size_t)((m < Mtot) ? m : 0) * Dd + k0 + u * 8;
                    if (m >= Mtot) sz = 0;
                } else {
                    src = Wz + (size_t)(col0 + r) * Dd + k0 + u * 8;
                }
                cp16(doff, src, sz);
            }
        } else {
#pragma unroll
            for (int i = 0; i < 4; i++) {
                const int v   = tid + i * 256;
                const int isB = v >> 9;                  // 0=Ah 1=B
                const int r   = (v >> 2) & 127;
                const int u   = v & 3;
                const uint32_t doff = stg + (isB ? 2 * TILE_B : 0) + r * ROWB + u * 16;
                const __half* src;
                uint32_t sz = 16;
                if (!isB) {
                    const int m = row0 + r;
                    src = g_Xh + (size_t)((m < Mtot) ? m : 0) * Dd + k0 + u * 8;
                    if (m >= Mtot) sz = 0;
                } else {
                    src = Wz + (size_t)(col0 + r) * Dd + k0 + u * 8;
                }
                cp16(doff, src, sz);
            }
        }
        cp_commit();
    };

    load_chunk(0, 0);

    for (int c = 0; c < NCHUNK; c++) {
        if (c + 1 < NCHUNK) { load_chunk(c + 1, (c + 1) & 1); cp_wait1(); }
        else                { cp_wait0(); }
        __syncthreads();

        const uint32_t stg = sb + (c & 1) * STAGE_B;
        const uint32_t aHi = stg + (wm * 64 + aRow) * ROWB + aKof * 2;
        const uint32_t bB  = stg + 2 * TILE_B + (wn * 32 + bRow) * ROWB + bKof * 2;

#pragma unroll
        for (int kk = 0; kk < 32; kk += 16) {
            uint32_t Ah[4][4], Al[4][4], Bf[4][2];
#pragma unroll
            for (int mi = 0; mi < 4; mi++) {
                const uint32_t a = aHi + mi * (16 * ROWB) + kk * 2;
                ldsm_x4(Ah[mi], a);
                if (twoPass) ldsm_x4(Al[mi], a + TILE_B);
            }
#pragma unroll
            for (int ni = 0; ni < 4; ni++)
                ldsm_x2(Bf[ni], bB + ni * (8 * ROWB) + kk * 2);
#pragma unroll
            for (int mi = 0; mi < 4; mi++)
#pragma unroll
                for (int ni = 0; ni < 4; ni++) {
                    mma_f16(acc[mi][ni], Ah[mi], Bf[ni]);
                    if (twoPass) mma_f16(acc[mi][ni], Al[mi], Bf[ni]);
                }
        }
        __syncthreads();
    }

    // epilogue: bias; single fp16 head-major scatter
    const int gq = lid >> 2;
    const int t  = lid & 3;
#pragma unroll
    for (int mi = 0; mi < 4; mi++) {
        const int m0 = row0 + wm * 64 + mi * 16 + gq;
#pragma unroll
        for (int half_ = 0; half_ < 2; half_++) {
            const int m = m0 + half_ * 8;
            if (m >= Mtot) continue;
            const int bix  = m / Ss;
            const int srow = m - bix * Ss;
#pragma unroll
            for (int ni = 0; ni < 4; ni++) {
                const int n = col0 + wn * 32 + ni * 8 + t * 2;
                const int h = n >> 6;
                const int d = n & 63;
                const float vx = acc[mi][ni][half_ * 2 + 0] + __ldg(bias + n);
                const float vy = acc[mi][ni][half_ * 2 + 1] + __ldg(bias + n + 1);
                const size_t idx = (((size_t)(bix * Hh + h) * Ss + srow) << 6) + d;
                __half2 h2 = __floats2half2_rn(vx, vy);
                *(uint32_t*)&OutH[idx] = *(uint32_t*)&h2;
            }
        }
    }
}

// ---------------------------------------------------------------------------
// Flash attention via mma.sync fp16, single-pass QK and PV.
// CTA = 128 Q rows of one (b,h); 8 warps x 16 rows; 128-key tiles.
// smem: Q (1 tile) + 2 stages x (K|V). Row stride 144B.
// ---------------------------------------------------------------------------
#define AKSTR   144
#define ATILE   (128 * AKSTR)            // 18432
#define ASTAGE  (2 * ATILE)              // 36864
#define AQ1     ATILE
#define ATTN_SMEM (AQ1 + 2 * ASTAGE)     // 92160
#define NTIL    ((Ss + 127) / 128)       // 11

__global__ __launch_bounds__(256, 1) void attn_mma(float* __restrict__ Out)
{
    extern __shared__ char smc[];
    const uint32_t sb = smem_u32(smc);
    const int tid = threadIdx.x;
    const int wid = tid >> 5;
    const int lid = tid & 31;
    const int qt  = blockIdx.x;
    const int h   = blockIdx.y;
    const int b   = blockIdx.z;

    const size_t bh = (size_t)(b * Hh + h) * Ss * HDim;

    auto load_q = [&]() {
#pragma unroll
        for (int i = 0; i < 4; i++) {
            const int u  = tid + i * 256;
            const int r  = (u >> 3) & 127;
            const int uc = u & 7;
            const int row = qt * 128 + r;
            const bool v = (row < Ss);
            const __half* gp = g_Q + bh + (size_t)(v ? row : 0) * HDim + uc * 8;
            cp16(sb + r * AKSTR + uc * 16, gp, v ? 16u : 0u);
        }
    };
    auto load_kv = [&](int kt, int s) {
        const uint32_t base = sb + AQ1 + s * ASTAGE;
#pragma unroll
        for (int i = 0; i < 8; i++) {
            const int u    = tid + i * 256;
            const int tile = u >> 10;           // 0=K 1=V
            const int r    = (u >> 3) & 127;
            const int uc   = u & 7;
            const int key  = kt * 128 + r;
            const bool v   = (key < Ss);
            const __half* gp = (tile == 0 ? g_K : g_V)
                + bh + (size_t)(v ? key : 0) * HDim + uc * 8;
            cp16(base + tile * ATILE + r * AKSTR + uc * 16, gp, v ? 16u : 0u);
        }
    };

    load_q();
    load_kv(0, 0);
    cp_commit();

    const int t  = lid & 3;
    const int gq = lid >> 2;
    const int kRow  = (lid & 7) + ((lid >> 4) & 1) * 8;
    const int kColB = ((lid >> 3) & 1) * 16;
    const int vRow  = (lid & 7) + ((lid >> 3) & 1) * 8;
    const int vColB = ((lid >> 4) & 1) * 16;

    float m0_ = -1e30f, m1_ = -1e30f, l0_ = 0.f, l1_ = 0.f;
    float O[8][4];
#pragma unroll
    for (int ni = 0; ni < 8; ni++)
#pragma unroll
        for (int q = 0; q < 4; q++) O[ni][q] = 0.f;

    uint32_t Qf[4][4];

    for (int kt = 0; kt < NTIL; kt++) {
        if (kt + 1 < NTIL) { load_kv(kt + 1, (kt + 1) & 1); cp_commit(); cp_wait1(); }
        else               { cp_wait0(); }
        __syncthreads();

        if (kt == 0) {
            const uint32_t qb = sb + (wid * 16 + vRow) * AKSTR + vColB;
#pragma unroll
            for (int ks = 0; ks < 4; ks++)
                ldsm_x4(Qf[ks], qb + ks * 32);
        }

        const uint32_t kb = sb + AQ1 + (kt & 1) * ASTAGE;

        // ---- S = Q K^T : single pass ----------------------------------------
        float SS[16][4];
#pragma unroll
        for (int ni = 0; ni < 16; ni++)
#pragma unroll
            for (int q = 0; q < 4; q++) SS[ni][q] = 0.f;

#pragma unroll
        for (int ks = 0; ks < 4; ks++) {
#pragma unroll
            for (int nip = 0; nip < 8; nip++) {
                uint32_t kf[4];
                ldsm_x4(kf, kb + (nip * 16 + kRow) * AKSTR + ks * 32 + kColB);
                mma_f16(SS[2 * nip],     Qf[ks], kf);
                mma_f16(SS[2 * nip + 1], Qf[ks], kf + 2);
            }
        }

        // ---- online softmax --------------------------------------------------
#pragma unroll
        for (int ni = 0; ni < 16; ni++)
#pragma unroll
            for (int q = 0; q < 4; q++) SS[ni][q] *= 0.125f;

        if (kt == NTIL - 1) {
            const int kb0 = kt * 128 + 2 * t;
#pragma unroll
            for (int ni = 0; ni < 16; ni++) {
                const int kk = kb0 + ni * 8;
                if (kk     >= Ss) { SS[ni][0] = -1e30f; SS[ni][2] = -1e30f; }
                if (kk + 1 >= Ss) { SS[ni][1] = -1e30f; SS[ni][3] = -1e30f; }
            }
        }

        float rm0 = -1e30f, rm1 = -1e30f;
#pragma unroll
        for (int ni = 0; ni < 16; ni++) {
            rm0 = fmaxf(rm0, fmaxf(SS[ni][0], SS[ni][1]));
            rm1 = fmaxf(rm1, fmaxf(SS[ni][2], SS[ni][3]));
        }
        rm0 = fmaxf(rm0, __shfl_xor_sync(0xffffffffu, rm0, 1));
        rm0 = fmaxf(rm0, __shfl_xor_sync(0xffffffffu, rm0, 2));
        rm1 = fmaxf(rm1, __shfl_xor_sync(0xffffffffu, rm1, 1));
        rm1 = fmaxf(rm1, __shfl_xor_sync(0xffffffffu, rm1, 2));

        const float mn0 = fmaxf(m0_, rm0);
        const float mn1 = fmaxf(m1_, rm1);
        const float a0  = __expf(m0_ - mn0);
        const float a1  = __expf(m1_ - mn1);
        m0_ = mn0; m1_ = mn1;

        float sum0 = 0.f, sum1 = 0.f;
#pragma unroll
        for (int ni = 0; ni < 16; ni++) {
            SS[ni][0] = __expf(SS[ni][0] - mn0);
            SS[ni][1] = __expf(SS[ni][1] - mn0);
            SS[ni][2] = __expf(SS[ni][2] - mn1);
            SS[ni][3] = __expf(SS[ni][3] - mn1);
            sum0 += SS[ni][0] + SS[ni][1];
            sum1 += SS[ni][2] + SS[ni][3];
        }
        sum0 += __shfl_xor_sync(0xffffffffu, sum0, 1);
        sum0 += __shfl_xor_sync(0xffffffffu, sum0, 2);
        sum1 += __shfl_xor_sync(0xffffffffu, sum1, 1);
        sum1 += __shfl_xor_sync(0xffffffffu, sum1, 2);
        l0_ = l0_ * a0 + sum0;
        l1_ = l1_ * a1 + sum1;

#pragma unroll
        for (int ni = 0; ni < 8; ni++) {
            O[ni][0] *= a0; O[ni][1] *= a0;
            O[ni][2] *= a1; O[ni][3] *= a1;
        }

        // ---- O += P V : P fp16 (reg-to-reg pack), single pass ----------------
        const uint32_t vb = kb + ATILE;
#pragma unroll
        for (int j = 0; j < 8; j++) {
            uint32_t ph[4];
            ph[0] = pack_h2(SS[2 * j][0],     SS[2 * j][1]);
            ph[1] = pack_h2(SS[2 * j][2],     SS[2 * j][3]);
            ph[2] = pack_h2(SS[2 * j + 1][0], SS[2 * j + 1][1]);
            ph[3] = pack_h2(SS[2 * j + 1][2], SS[2 * j + 1][3]);
#pragma unroll
            for (int nip = 0; nip < 4; nip++) {
                uint32_t vh[4];
                ldsm_x4t(vh, vb + (j * 16 + vRow) * AKSTR + nip * 32 + vColB);
                mma_f16(O[2 * nip],     ph, vh);
                mma_f16(O[2 * nip + 1], ph, vh + 2);
            }
        }
        __syncthreads();
    }

    // ---- epilogue -----------------------------------------------------------
    const int r0 = qt * 128 + wid * 16 + gq;
    const int r1 = r0 + 8;
    const float inv0 = 1.f / l0_;
    const float inv1 = 1.f / l1_;
#pragma unroll
    for (int ni = 0; ni < 8; ni++) {
        const int d = h * HDim + ni * 8 + 2 * t;
        if (r0 < Ss)
            *(float2*)&Out[((size_t)b * Ss + r0) * Dd + d] =
                make_float2(O[ni][0] * inv0, O[ni][1] * inv0);
        if (r1 < Ss)
            *(float2*)&Out[((size_t)b * Ss + r1) * Dd + d] =
                make_float2(O[ni][2] * inv1, O[ni][3] * inv1);
    }
}

// ---------------------------------------------------------------------------
extern "C" void kernel_launch(void* const* d_in, const int* in_sizes, int n_in,
                              void* d_out, int out_size)
{
    const float* X  = (const float*)d_in[0];
    const float* Wq = (const float*)d_in[1];
    const float* bq = (const float*)d_in[2];
    const float* Wk = (const float*)d_in[3];
    const float* bk = (const float*)d_in[4];
    const float* Wv = (const float*)d_in[5];
    const float* bv = (const float*)d_in[6];
    float* out = (float*)d_out;

    const int nX4 = Mtot * Dd / 4;
    const int nW4 = Dd * Dd / 4;
    split_kernel<<<(nX4 + 255) / 256, 256>>>(X, 0, nX4);
    split_kernel<<<(nW4 + 255) / 256, 256>>>(Wq, 1, nW4);
    split_kernel<<<(nW4 + 255) / 256, 256>>>(Wk, 2, nW4);
    split_kernel<<<(nW4 + 255) / 256, 256>>>(Wv, 3, nW4);

    cudaFuncSetAttribute(qkv_gemm_mma, cudaFuncAttributeMaxDynamicSharedMemorySize,
                         GEMM_SMEM);
    dim3 gg(Dd / 128, (Mtot + 127) / 128, 3);
    qkv_gemm_mma<<<gg, 256, GEMM_SMEM>>>(bq, bk, bv);

    cudaFuncSetAttribute(attn_mma, cudaFuncAttributeMaxDynamicSharedMemorySize,
                         ATTN_SMEM);
    dim3 g2((Ss + 127) / 128, Hh, Bb);          // (11, 16, 8)
    attn_mma<<<g2, 256, ATTN_SMEM>>>(out);
}

// round 17
// speedup vs baseline: 5.1524x; 1.0840x over previous
#include <cuda_runtime.h>
#include <cuda_fp16.h>
#include <math.h>
#include <stdint.h>

// Problem constants
#define Bb   8
#define Ss   1370
#define Dd   1024
#define Hh   16
#define HDim 64
#define Mtot (Bb * Ss)          // 10960

// ---------------------------------------------------------------------------
// Static device scratch (allocation-free)
// ---------------------------------------------------------------------------
__device__ __half g_Xh[Mtot * Dd];      // X hi (fp16)
__device__ __half g_Xl[Mtot * Dd];      // X lo (fp16 residual)
__device__ __half g_W [3 * Dd * Dd];    // Wq|Wk|Wv single fp16

// head-major [B,H,S,64], all single fp16
__device__ __half g_Q[Bb * Hh * Ss * HDim];
__device__ __half g_K[Bb * Hh * Ss * HDim];
__device__ __half g_V[Bb * Hh * Ss * HDim];

// ---------------------------------------------------------------------------
// PTX helpers — arch-generic only (no tcgen05: harness ptx target is bare 103)
// ---------------------------------------------------------------------------
__device__ __forceinline__ uint32_t smem_u32(const void* p) {
    uint32_t a;
    asm("{ .reg .u64 t; cvta.to.shared.u64 t, %1; cvt.u32.u64 %0, t; }"
        : "=r"(a) : "l"(p));
    return a;
}
__device__ __forceinline__ void cp16(uint32_t d, const void* s, uint32_t sz) {
    asm volatile("cp.async.cg.shared.global [%0], [%1], 16, %2;"
                 :: "r"(d), "l"(s), "r"(sz) : "memory");
}
__device__ __forceinline__ void cp_commit() {
    asm volatile("cp.async.commit_group;" ::: "memory");
}
__device__ __forceinline__ void cp_wait1() {
    asm volatile("cp.async.wait_group 1;" ::: "memory");
}
__device__ __forceinline__ void cp_wait0() {
    asm volatile("cp.async.wait_group 0;" ::: "memory");
}
__device__ __forceinline__ void ldsm_x4(uint32_t* r, uint32_t addr) {
    asm volatile("ldmatrix.sync.aligned.m8n8.x4.shared.b16 {%0,%1,%2,%3}, [%4];"
                 : "=r"(r[0]), "=r"(r[1]), "=r"(r[2]), "=r"(r[3]) : "r"(addr));
}
__device__ __forceinline__ void ldsm_x4t(uint32_t* r, uint32_t addr) {
    asm volatile("ldmatrix.sync.aligned.m8n8.x4.trans.shared.b16 {%0,%1,%2,%3}, [%4];"
                 : "=r"(r[0]), "=r"(r[1]), "=r"(r[2]), "=r"(r[3]) : "r"(addr));
}
__device__ __forceinline__ void mma_f16(float* c, const uint32_t* a, const uint32_t* b) {
    asm volatile(
        "mma.sync.aligned.m16n8k16.row.col.f32.f16.f16.f32 "
        "{%0,%1,%2,%3}, {%4,%5,%6,%7}, {%8,%9}, {%0,%1,%2,%3};"
        : "+f"(c[0]), "+f"(c[1]), "+f"(c[2]), "+f"(c[3])
        : "r"(a[0]), "r"(a[1]), "r"(a[2]), "r"(a[3]), "r"(b[0]), "r"(b[1]));
}
__device__ __forceinline__ uint32_t pack_h2(float x, float y) {
    __half2 h = __floats2half2_rn(x, y);
    return *reinterpret_cast<uint32_t*>(&h);
}

// ---------------------------------------------------------------------------
// fp32 -> fp16.  mode 0: X -> hi + lo residual.  modes 1..3: W -> single fp16.
// ---------------------------------------------------------------------------
__global__ void split_kernel(const float* __restrict__ src, int mode, int n4)
{
    int i = blockIdx.x * blockDim.x + threadIdx.x;
    if (i >= n4) return;
    float4 v = ((const float4*)src)[i];
    if (mode == 0) {
        __half2 h01 = __floats2half2_rn(v.x, v.y);
        __half2 h23 = __floats2half2_rn(v.z, v.w);
        float2 f01 = __half22float2(h01);
        float2 f23 = __half22float2(h23);
        __half2 l01 = __floats2half2_rn(v.x - f01.x, v.y - f01.y);
        __half2 l23 = __floats2half2_rn(v.z - f23.x, v.w - f23.y);
        ((__half2*)g_Xh)[2 * i]     = h01;
        ((__half2*)g_Xh)[2 * i + 1] = h23;
        ((__half2*)g_Xl)[2 * i]     = l01;
        ((__half2*)g_Xl)[2 * i + 1] = l23;
    } else {
        __half* w = g_W + (size_t)(mode - 1) * Dd * Dd;
        ((__half2*)w)[2 * i]     = __floats2half2_rn(v.x, v.y);
        ((__half2*)w)[2 * i + 1] = __floats2half2_rn(v.z, v.w);
    }
}

// ---------------------------------------------------------------------------
// QKV GEMM via mma.sync fp16.
// Q (z==0): 2-pass (Xh+Xl)@W^T.  K,V: 1-pass Xh@W^T.
// CTA 128x128, BK=64, 512 threads = 16 warps (4Mx4N), warp tile 32x32.
// smem per stage: Ah | Al | B tiles, 128 rows x 64 fp16, row stride 144B.
// ---------------------------------------------------------------------------
#define ROWB     144
#define TILE_B   (128 * ROWB)             // 18432
#define STAGE_B  (3 * TILE_B)             // 55296
#define GEMM_SMEM (2 * STAGE_B)           // 110592
#define NCHUNK   (Dd / 64)                // 16

__global__ __launch_bounds__(512, 1) void qkv_gemm_mma(
    const float* __restrict__ bq, const float* __restrict__ bk,
    const float* __restrict__ bv)
{
    extern __shared__ char smc[];
    const uint32_t sb = smem_u32(smc);
    const int tid = threadIdx.x;
    const int wid = tid >> 5;
    const int lid = tid & 31;

    const int nt = blockIdx.x;
    const int mt = blockIdx.y;
    const int z  = blockIdx.z;
    const int row0 = mt * 128;
    const int col0 = nt * 128;
    const bool twoPass = (z == 0);

    const __half* __restrict__ Wz = g_W + (size_t)z * Dd * Dd;
    const float* __restrict__ bias = (z == 0) ? bq : (z == 1) ? bk : bv;
    __half* __restrict__ OutH = (z == 0) ? g_Q : (z == 1) ? g_K : g_V;

    const int wm = wid & 3;             // M group of 32 rows
    const int wn = wid >> 2;            // N group of 32 cols
    // A-fragment addressing (m16k16 via ldsm_x4)
    const int aRow = lid & 15;
    const int aKof = (lid >> 4) * 8;
    // B-pair addressing (two n8k16 frags via one ldsm_x4)
    const int kRow  = (lid & 7) + ((lid >> 4) & 1) * 8;
    const int kColB = ((lid >> 3) & 1) * 16;

    float acc[2][4][4];
#pragma unroll
    for (int mi = 0; mi < 2; mi++)
#pragma unroll
        for (int ni = 0; ni < 4; ni++)
#pragma unroll
            for (int q = 0; q < 4; q++) acc[mi][ni][q] = 0.f;

    // ---- producer: BK=64 chunk = 128 rows x 8 x 16B data units per tile ----
    auto load_chunk = [&](int c, int s) {
        const uint32_t stg = sb + s * STAGE_B;
        const int k0 = c * 64;
        if (twoPass) {
#pragma unroll
            for (int i = 0; i < 6; i++) {           // 3072 units / 512
                const int v    = tid + i * 512;
                const int tile = v >> 10;           // 0=Ah 1=Al 2=B
                const int r    = (v >> 3) & 127;
                const int u    = v & 7;
                const uint32_t doff = stg + tile * TILE_B + r * ROWB + u * 16;
                const __half* src;
                uint32_t sz = 16;
                if (tile < 2) {
                    const int m = row0 + r;
                    const __half* base = (tile == 0) ? g_Xh : g_Xl;
                    src = base + (size_t)((m < Mtot) ? m : 0) * Dd + k0 + u * 8;
                    if (m >= Mtot) sz = 0;
                } else {
                    src = Wz + (size_t)(col0 + r) * Dd + k0 + u * 8;
                }
                cp16(doff, src, sz);
            }
        } else {
#pragma unroll
            for (int i = 0; i < 4; i++) {           // 2048 units / 512
                const int v   = tid + i * 512;
                const int isB = v >> 10;            // 0=Ah 1=B
                const int r   = (v >> 3) & 127;
                const int u   = v & 7;
                const uint32_t doff = stg + (isB ? 2 * TILE_B : 0) + r * ROWB + u * 16;
                const __half* src;
                uint32_t sz = 16;
                if (!isB) {
                    const int m = row0 + r;
                    src = g_Xh + (size_t)((m < Mtot) ? m : 0) * Dd + k0 + u * 8;
                    if (m >= Mtot) sz = 0;
                } else {
                    src = Wz + (size_t)(col0 + r) * Dd + k0 + u * 8;
                }
                cp16(doff, src, sz);
            }
        }
        cp_commit();
    };

    load_chunk(0, 0);

    for (int c = 0; c < NCHUNK; c++) {
        if (c + 1 < NCHUNK) { load_chunk(c + 1, (c + 1) & 1); cp_wait1(); }
        else                { cp_wait0(); }
        __syncthreads();

        const uint32_t stg   = sb + (c & 1) * STAGE_B;
        const uint32_t aBase = stg + (wm * 32 + aRow) * ROWB + aKof * 2;
        const uint32_t bBase = stg + 2 * TILE_B + (wn * 32 + kRow) * ROWB + kColB;

#pragma unroll
        for (int kk = 0; kk < 64; kk += 16) {
            uint32_t Ah[2][4], Al[2][4], Bf[2][4];
#pragma unroll
            for (int mi = 0; mi < 2; mi++) {
                const uint32_t a = aBase + mi * (16 * ROWB) + kk * 2;
                ldsm_x4(Ah[mi], a);
                if (twoPass) ldsm_x4(Al[mi], a + TILE_B);
            }
#pragma unroll
            for (int nb = 0; nb < 2; nb++)
                ldsm_x4(Bf[nb], bBase + nb * (16 * ROWB) + kk * 2);
#pragma unroll
            for (int mi = 0; mi < 2; mi++)
#pragma unroll
                for (int nb = 0; nb < 2; nb++) {
                    mma_f16(acc[mi][2 * nb],     Ah[mi], Bf[nb]);
                    mma_f16(acc[mi][2 * nb + 1], Ah[mi], Bf[nb] + 2);
                    if (twoPass) {
                        mma_f16(acc[mi][2 * nb],     Al[mi], Bf[nb]);
                        mma_f16(acc[mi][2 * nb + 1], Al[mi], Bf[nb] + 2);
                    }
                }
        }
        __syncthreads();
    }

    // epilogue: bias; single fp16 head-major scatter
    const int gq = lid >> 2;
    const int t  = lid & 3;
#pragma unroll
    for (int mi = 0; mi < 2; mi++) {
        const int m0 = row0 + wm * 32 + mi * 16 + gq;
#pragma unroll
        for (int half_ = 0; half_ < 2; half_++) {
            const int m = m0 + half_ * 8;
            if (m >= Mtot) continue;
            const int bix  = m / Ss;
            const int srow = m - bix * Ss;
#pragma unroll
            for (int ni = 0; ni < 4; ni++) {
                const int n = col0 + wn * 32 + ni * 8 + t * 2;
                const int h = n >> 6;
                const int d = n & 63;
                const float vx = acc[mi][ni][half_ * 2 + 0] + __ldg(bias + n);
                const float vy = acc[mi][ni][half_ * 2 + 1] + __ldg(bias + n + 1);
                const size_t idx = (((size_t)(bix * Hh + h) * Ss + srow) << 6) + d;
                __half2 h2 = __floats2half2_rn(vx, vy);
                *(uint32_t*)&OutH[idx] = *(uint32_t*)&h2;
            }
        }
    }
}

// ---------------------------------------------------------------------------
// Flash attention via mma.sync fp16, single-pass QK and PV. (unchanged)
// CTA = 128 Q rows of one (b,h); 8 warps x 16 rows; 128-key tiles.
// smem: Q (1 tile) + 2 stages x (K|V). Row stride 144B.
// ---------------------------------------------------------------------------
#define AKSTR   144
#define ATILE   (128 * AKSTR)            // 18432
#define ASTAGE  (2 * ATILE)              // 36864
#define AQ1     ATILE
#define ATTN_SMEM (AQ1 + 2 * ASTAGE)     // 92160
#define NTIL    ((Ss + 127) / 128)       // 11

__global__ __launch_bounds__(256, 1) void attn_mma(float* __restrict__ Out)
{
    extern __shared__ char smc[];
    const uint32_t sb = smem_u32(smc);
    const int tid = threadIdx.x;
    const int wid = tid >> 5;
    const int lid = tid & 31;
    const int qt  = blockIdx.x;
    const int h   = blockIdx.y;
    const int b   = blockIdx.z;

    const size_t bh = (size_t)(b * Hh + h) * Ss * HDim;

    auto load_q = [&]() {
#pragma unroll
        for (int i = 0; i < 4; i++) {
            const int u  = tid + i * 256;
            const int r  = (u >> 3) & 127;
            const int uc = u & 7;
            const int row = qt * 128 + r;
            const bool v = (row < Ss);
            const __half* gp = g_Q + bh + (size_t)(v ? row : 0) * HDim + uc * 8;
            cp16(sb + r * AKSTR + uc * 16, gp, v ? 16u : 0u);
        }
    };
    auto load_kv = [&](int kt, int s) {
        const uint32_t base = sb + AQ1 + s * ASTAGE;
#pragma unroll
        for (int i = 0; i < 8; i++) {
            const int u    = tid + i * 256;
            const int tile = u >> 10;           // 0=K 1=V
            const int r    = (u >> 3) & 127;
            const int uc   = u & 7;
            const int key  = kt * 128 + r;
            const bool v   = (key < Ss);
            const __half* gp = (tile == 0 ? g_K : g_V)
                + bh + (size_t)(v ? key : 0) * HDim + uc * 8;
            cp16(base + tile * ATILE + r * AKSTR + uc * 16, gp, v ? 16u : 0u);
        }
    };

    load_q();
    load_kv(0, 0);
    cp_commit();

    const int t  = lid & 3;
    const int gq = lid >> 2;
    const int kRow  = (lid & 7) + ((lid >> 4) & 1) * 8;
    const int kColB = ((lid >> 3) & 1) * 16;
    const int vRow  = (lid & 7) + ((lid >> 3) & 1) * 8;
    const int vColB = ((lid >> 4) & 1) * 16;

    float m0_ = -1e30f, m1_ = -1e30f, l0_ = 0.f, l1_ = 0.f;
    float O[8][4];
#pragma unroll
    for (int ni = 0; ni < 8; ni++)
#pragma unroll
        for (int q = 0; q < 4; q++) O[ni][q] = 0.f;

    uint32_t Qf[4][4];

    for (int kt = 0; kt < NTIL; kt++) {
        if (kt + 1 < NTIL) { load_kv(kt + 1, (kt + 1) & 1); cp_commit(); cp_wait1(); }
        else               { cp_wait0(); }
        __syncthreads();

        if (kt == 0) {
            const uint32_t qb = sb + (wid * 16 + vRow) * AKSTR + vColB;
#pragma unroll
            for (int ks = 0; ks < 4; ks++)
                ldsm_x4(Qf[ks], qb + ks * 32);
        }

        const uint32_t kb = sb + AQ1 + (kt & 1) * ASTAGE;

        // ---- S = Q K^T : single pass ----------------------------------------
        float SS[16][4];
#pragma unroll
        for (int ni = 0; ni < 16; ni++)
#pragma unroll
            for (int q = 0; q < 4; q++) SS[ni][q] = 0.f;

#pragma unroll
        for (int ks = 0; ks < 4; ks++) {
#pragma unroll
            for (int nip = 0; nip < 8; nip++) {
                uint32_t kf[4];
                ldsm_x4(kf, kb + (nip * 16 + kRow) * AKSTR + ks * 32 + kColB);
                mma_f16(SS[2 * nip],     Qf[ks], kf);
                mma_f16(SS[2 * nip + 1], Qf[ks], kf + 2);
            }
        }

        // ---- online softmax --------------------------------------------------
#pragma unroll
        for (int ni = 0; ni < 16; ni++)
#pragma unroll
            for (int q = 0; q < 4; q++) SS[ni][q] *= 0.125f;

        if (kt == NTIL - 1) {
            const int kb0 = kt * 128 + 2 * t;
#pragma unroll
            for (int ni = 0; ni < 16; ni++) {
                const int kk = kb0 + ni * 8;
                if (kk     >= Ss) { SS[ni][0] = -1e30f; SS[ni][2] = -1e30f; }
                if (kk + 1 >= Ss) { SS[ni][1] = -1e30f; SS[ni][3] = -1e30f; }
            }
        }

        float rm0 = -1e30f, rm1 = -1e30f;
#pragma unroll
        for (int ni = 0; ni < 16; ni++) {
            rm0 = fmaxf(rm0, fmaxf(SS[ni][0], SS[ni][1]));
            rm1 = fmaxf(rm1, fmaxf(SS[ni][2], SS[ni][3]));
        }
        rm0 = fmaxf(rm0, __shfl_xor_sync(0xffffffffu, rm0, 1));
        rm0 = fmaxf(rm0, __shfl_xor_sync(0xffffffffu, rm0, 2));
        rm1 = fmaxf(rm1, __shfl_xor_sync(0xffffffffu, rm1, 1));
        rm1 = fmaxf(rm1, __shfl_xor_sync(0xffffffffu, rm1, 2));

        const float mn0 = fmaxf(m0_, rm0);
        const float mn1 = fmaxf(m1_, rm1);
        const float a0  = __expf(m0_ - mn0);
        const float a1  = __expf(m1_ - mn1);
        m0_ = mn0; m1_ = mn1;

        float sum0 = 0.f, sum1 = 0.f;
#pragma unroll
        for (int ni = 0; ni < 16; ni++) {
            SS[ni][0] = __expf(SS[ni][0] - mn0);
            SS[ni][1] = __expf(SS[ni][1] - mn0);
            SS[ni][2] = __expf(SS[ni][2] - mn1);
            SS[ni][3] = __expf(SS[ni][3] - mn1);
            sum0 += SS[ni][0] + SS[ni][1];
            sum1 += SS[ni][2] + SS[ni][3];
        }
        sum0 += __shfl_xor_sync(0xffffffffu, sum0, 1);
        sum0 += __shfl_xor_sync(0xffffffffu, sum0, 2);
        sum1 += __shfl_xor_sync(0xffffffffu, sum1, 1);
        sum1 += __shfl_xor_sync(0xffffffffu, sum1, 2);
        l0_ = l0_ * a0 + sum0;
        l1_ = l1_ * a1 + sum1;

#pragma unroll
        for (int ni = 0; ni < 8; ni++) {
            O[ni][0] *= a0; O[ni][1] *= a0;
            O[ni][2] *= a1; O[ni][3] *= a1;
        }

        // ---- O += P V : P fp16 (reg-to-reg pack), single pass ----------------
        const uint32_t vb = kb + ATILE;
#pragma unroll
        for (int j = 0; j < 8; j++) {
            uint32_t ph[4];
            ph[0] = pack_h2(SS[2 * j][0],     SS[2 * j][1]);
            ph[1] = pack_h2(SS[2 * j][2],     SS[2 * j][3]);
            ph[2] = pack_h2(SS[2 * j + 1][0], SS[2 * j + 1][1]);
            ph[3] = pack_h2(SS[2 * j + 1][2], SS[2 * j + 1][3]);
#pragma unroll
            for (int nip = 0; nip < 4; nip++) {
                uint32_t vh[4];
                ldsm_x4t(vh, vb + (j * 16 + vRow) * AKSTR + nip * 32 + vColB);
                mma_f16(O[2 * nip],     ph, vh);
                mma_f16(O[2 * nip + 1], ph, vh + 2);
            }
        }
        __syncthreads();
    }

    // ---- epilogue -----------------------------------------------------------
    const int r0 = qt * 128 + wid * 16 + gq;
    const int r1 = r0 + 8;
    const float inv0 = 1.f / l0_;
    const float inv1 = 1.f / l1_;
#pragma unroll
    for (int ni = 0; ni < 8; ni++) {
        const int d = h * HDim + ni * 8 + 2 * t;
        if (r0 < Ss)
            *(float2*)&Out[((size_t)b * Ss + r0) * Dd + d] =
                make_float2(O[ni][0] * inv0, O[ni][1] * inv0);
        if (r1 < Ss)
            *(float2*)&Out[((size_t)b * Ss + r1) * Dd + d] =
                make_float2(O[ni][2] * inv1, O[ni][3] * inv1);
    }
}

// ---------------------------------------------------------------------------
extern "C" void kernel_launch(void* const* d_in, const int* in_sizes, int n_in,
                              void* d_out, int out_size)
{
    const float* X  = (const float*)d_in[0];
    const float* Wq = (const float*)d_in[1];
    const float* bq = (const float*)d_in[2];
    const float* Wk = (const float*)d_in[3];
    const float* bk = (const float*)d_in[4];
    const float* Wv = (const float*)d_in[5];
    const float* bv = (const float*)d_in[6];
    float* out = (float*)d_out;

    const int nX4 = Mtot * Dd / 4;
    const int nW4 = Dd * Dd / 4;
    split_kernel<<<(nX4 + 255) / 256, 256>>>(X, 0, nX4);
    split_kernel<<<(nW4 + 255) / 256, 256>>>(Wq, 1, nW4);
    split_kernel<<<(nW4 + 255) / 256, 256>>>(Wk, 2, nW4);
    split_kernel<<<(nW4 + 255) / 256, 256>>>(Wv, 3, nW4);

    cudaFuncSetAttribute(qkv_gemm_mma, cudaFuncAttributeMaxDynamicSharedMemorySize,
                         GEMM_SMEM);
    dim3 gg(Dd / 128, (Mtot + 127) / 128, 3);   // (8, 86, 3)
    qkv_gemm_mma<<<gg, 512, GEMM_SMEM>>>(bq, bk, bv);

    cudaFuncSetAttribute(attn_mma, cudaFuncAttributeMaxDynamicSharedMemorySize,
                         ATTN_SMEM);
    dim3 g2((Ss + 127) / 128, Hh, Bb);          // (11, 16, 8)
    attn_mma<<<g2, 256, ATTN_SMEM>>>(out);
}